// round 13
// baseline (speedup 1.0000x reference)
#include <cuda_runtime.h>
#include <cuda_bf16.h>
#include <cstdint>

// ---------------------------------------------------------------------------
// ConvSwinTransformerBlock  (B=4, H=W=128, C=384, WS=8, SHIFT=4, HEADS=12)
// R13: R12 + bf16 shadow copy of x1 for dwconv7 (halves its L1 bytes);
//      fp32 x1 kept for the GEMM2 residual path.
// ---------------------------------------------------------------------------

#define CC 384
#define NWIN 1024             // 4 * 256

extern __shared__ char dyn_smem[];

// ---------------- scratch (device globals: allocation-guard safe) ----------
__device__ __nv_bfloat16 g_qb [25165824];       // [win*12+hd][64][32]
__device__ __nv_bfloat16 g_kb [25165824];
__device__ __nv_bfloat16 g_vb [25165824];
__device__ __nv_bfloat16 g_aob[25165824];       // attn out, bf16
__device__ float g_x1 [25165824];               // fp32 (residual for GEMM2)
__device__ __nv_bfloat16 g_x1b[25165824];       // bf16 shadow (dwconv7 input)
__device__ __nv_bfloat16 g_m0b[25165824];       // dwconv7 out, bf16
__device__ __nv_bfloat16 g_m1 [25165824];
__device__ __nv_bfloat16 g_h  [100663296];      // 65536 x 1536
__device__ __nv_bfloat16 g_w1t[589824];         // [1536][384]
__device__ __nv_bfloat16 g_w2t[589824];         // [384][1536]

__device__ __forceinline__ float gelu_exact(float x) {
    return 0.5f * x * (1.0f + erff(x * 0.7071067811865476f));
}
__device__ __forceinline__ unsigned packbf(float a, float b) {
    __nv_bfloat162 v = __floats2bfloat162_rn(a, b);
    return *(unsigned*)&v;
}

// ---------------- LayerNorm bf16->bf16 over C=384 (warp per token) ---------
__global__ void ln_bf_kernel(const __nv_bfloat16* __restrict__ in,
                             __nv_bfloat16* __restrict__ out,
                             const float* __restrict__ g,
                             const float* __restrict__ bta, float eps) {
    int token = blockIdx.x * 8 + (threadIdx.x >> 5);
    int lane = threadIdx.x & 31;
    const __nv_bfloat162* p = (const __nv_bfloat162*)(in + (size_t)token * CC);
    float2 v[6];
    float s = 0.f, s2 = 0.f;
#pragma unroll
    for (int i = 0; i < 6; i++) {
        v[i] = __bfloat1622float2(p[lane + 32 * i]);
        s += v[i].x + v[i].y;
        s2 += v[i].x * v[i].x + v[i].y * v[i].y;
    }
#pragma unroll
    for (int o = 16; o; o >>= 1) {
        s += __shfl_xor_sync(0xffffffffu, s, o);
        s2 += __shfl_xor_sync(0xffffffffu, s2, o);
    }
    float mu = s * (1.f / 384.f);
    float var = s2 * (1.f / 384.f) - mu * mu;
    float rstd = rsqrtf(var + eps);
    __nv_bfloat162* q = (__nv_bfloat162*)(out + (size_t)token * CC);
    const float2* g2 = (const float2*)g;
    const float2* b2 = (const float2*)bta;
#pragma unroll
    for (int i = 0; i < 6; i++) {
        int j = lane + 32 * i;
        float2 gg = g2[j], bb = b2[j];
        q[j] = __floats2bfloat162_rn((v[i].x - mu) * rstd * gg.x + bb.x,
                                     (v[i].y - mu) * rstd * gg.y + bb.y);
    }
}

// ---------------- QKV: LN1(reg) -> bf16 window -> dwconv3x3 -> LN ----------
// smem: xs (64*384 bf16 = 49152 B) + ws (3456 f32 = 13824 B) = 62976 B
__global__ __launch_bounds__(256) void qkv_kernel(
    const float* __restrict__ x, const float* __restrict__ n1g,
    const float* __restrict__ n1b,
    const float* __restrict__ wq, const float* __restrict__ lnqg,
    const float* __restrict__ lnqb,
    const float* __restrict__ wk, const float* __restrict__ lnkg,
    const float* __restrict__ lnkb,
    const float* __restrict__ wv, const float* __restrict__ lnvg,
    const float* __restrict__ lnvb) {
    __nv_bfloat16* xs = (__nv_bfloat16*)dyn_smem;          // 64*384 bf16
    float* ws = (float*)(dyn_smem + 49152);                // 3456 floats
    uint2* xs_u2 = (uint2*)xs;                             // 96 uint2 per token
    int tid = threadIdx.x;
    int win = blockIdx.x;
    int b = win >> 8, widx = win & 255, wh = widx >> 4, ww = widx & 15;
    int warp = tid >> 5, lane = tid & 31;

    // ---- phase 1: load + LN1 in registers, write bf16 window ----
    for (int t = warp; t < 64; t += 8) {
        int r = t >> 3, cc0 = t & 7;
        int h = (wh * 8 + r + 4) & 127;
        int w = (ww * 8 + cc0 + 4) & 127;
        const float4* src = (const float4*)x + (size_t)(b * 16384 + h * 128 + w) * 96;
        float4 xv[3];
        float s = 0.f, s2 = 0.f;
#pragma unroll
        for (int g = 0; g < 3; g++) {
            xv[g] = __ldg(src + g * 32 + lane);
            s += xv[g].x + xv[g].y + xv[g].z + xv[g].w;
            s2 += xv[g].x * xv[g].x + xv[g].y * xv[g].y +
                  xv[g].z * xv[g].z + xv[g].w * xv[g].w;
        }
#pragma unroll
        for (int o = 16; o; o >>= 1) {
            s += __shfl_xor_sync(0xffffffffu, s, o);
            s2 += __shfl_xor_sync(0xffffffffu, s2, o);
        }
        float mu = s * (1.f / 384.f);
        float var = s2 * (1.f / 384.f) - mu * mu;
        float rstd = rsqrtf(var + 1e-5f);
#pragma unroll
        for (int g = 0; g < 3; g++) {
            int c4 = g * 32 + lane;
            float4 g4 = ((const float4*)n1g)[c4];
            float4 b4 = ((const float4*)n1b)[c4];
            float ox = (xv[g].x - mu) * rstd * g4.x + b4.x;
            float oy = (xv[g].y - mu) * rstd * g4.y + b4.y;
            float oz = (xv[g].z - mu) * rstd * g4.z + b4.z;
            float ow = (xv[g].w - mu) * rstd * g4.w + b4.w;
            uint2 pk;
            pk.x = packbf(ox, oy);
            pk.y = packbf(oz, ow);
            xs_u2[t * 96 + c4] = pk;
        }
    }
    __syncthreads();

    const float* Wp[3] = {wq, wk, wv};
    const float* Gg[3] = {lnqg, lnkg, lnvg};
    const float* Bb[3] = {lnqb, lnkb, lnvb};
    __nv_bfloat16* Out[3] = {g_qb, g_kb, g_vb};
    const float4* ws4 = (const float4*)ws;
    int cc = warp;   // column this warp owns

    for (int p = 0; p < 3; p++) {
        for (int i = tid; i < 3456; i += 256) ws[i] = Wp[p][i];
        __syncthreads();
        float scale = (p == 0) ? 0.17677669529663687f : 1.0f;  // 1/sqrt(32)

        for (int m = 0; m < 4; m++) {
            int rA = 2 * m;                    // token rows rA, rA+1
            float4 a0[3], a1[3];
#pragma unroll
            for (int g = 0; g < 3; g++) {
                a0[g] = make_float4(0.f, 0.f, 0.f, 0.f);
                a1[g] = make_float4(0.f, 0.f, 0.f, 0.f);
            }
            {
                float4 wcur[9], wprev[9];      // scoped: freed before LN
#pragma unroll
                for (int dr2 = 0; dr2 < 4; dr2++) {
                    if (dr2 > 0) {
#pragma unroll
                        for (int i = 0; i < 9; i++) wprev[i] = wcur[i];
                    }
                    if (dr2 <= 2) {
#pragma unroll
                        for (int dc = 0; dc < 3; dc++)
#pragma unroll
                            for (int g = 0; g < 3; g++)
                                wcur[dc * 3 + g] = ws4[(dr2 * 3 + dc) * 96 + g * 32 + lane];
                    }
                    int rr = rA - 1 + dr2;
                    if (rr < 0 || rr > 7) continue;
                    bool u0 = (dr2 <= 2);      // token row rA uses tap row dr2
                    bool u1 = (dr2 >= 1);      // token row rA+1 uses tap row dr2-1
#pragma unroll
                    for (int dc = 0; dc < 3; dc++) {
                        int c2 = cc + dc - 1;
                        if (c2 < 0 || c2 > 7) continue;
#pragma unroll
                        for (int g = 0; g < 3; g++) {
                            uint2 xv2 = xs_u2[(rr * 8 + c2) * 96 + g * 32 + lane];
                            float2 f01 = __bfloat1622float2(*(__nv_bfloat162*)&xv2.x);
                            float2 f23 = __bfloat1622float2(*(__nv_bfloat162*)&xv2.y);
                            if (u0) {
                                float4 w = wcur[dc * 3 + g];
                                a0[g].x += f01.x * w.x; a0[g].y += f01.y * w.y;
                                a0[g].z += f23.x * w.z; a0[g].w += f23.y * w.w;
                            }
                            if (u1) {
                                float4 w = wprev[dc * 3 + g];
                                a1[g].x += f01.x * w.x; a1[g].y += f01.y * w.y;
                                a1[g].z += f23.x * w.z; a1[g].w += f23.y * w.w;
                            }
                        }
                    }
                }
            }
            // ---- LN + store for the two tokens (fused sum/sumsq) ----
#pragma unroll
            for (int half = 0; half < 2; half++) {
                float4* vv = half ? a1 : a0;
                int t = (rA + half) * 8 + cc;
                float s = 0.f, s2 = 0.f;
#pragma unroll
                for (int g = 0; g < 3; g++) {
                    s += vv[g].x + vv[g].y + vv[g].z + vv[g].w;
                    s2 += vv[g].x * vv[g].x + vv[g].y * vv[g].y +
                          vv[g].z * vv[g].z + vv[g].w * vv[g].w;
                }
#pragma unroll
                for (int o = 16; o; o >>= 1) {
                    s += __shfl_xor_sync(0xffffffffu, s, o);
                    s2 += __shfl_xor_sync(0xffffffffu, s2, o);
                }
                float mu = s * (1.f / 384.f);
                float var = s2 * (1.f / 384.f) - mu * mu;
                float rstd = rsqrtf(var + 1e-5f);
#pragma unroll
                for (int g = 0; g < 3; g++) {
                    int c4 = g * 32 + lane;
                    float4 g4 = ((const float4*)Gg[p])[c4];
                    float4 b4 = ((const float4*)Bb[p])[c4];
                    float ox = ((vv[g].x - mu) * rstd * g4.x + b4.x) * scale;
                    float oy = ((vv[g].y - mu) * rstd * g4.y + b4.y) * scale;
                    float oz = ((vv[g].z - mu) * rstd * g4.z + b4.z) * scale;
                    float ow = ((vv[g].w - mu) * rstd * g4.w + b4.w) * scale;
                    int head = c4 >> 3, d0 = (c4 & 7) * 4;
                    __nv_bfloat16* dst = Out[p] +
                        ((size_t)(win * 12 + head) * 64 + t) * 32 + d0;
                    uint2 pk;
                    pk.x = packbf(ox, oy);
                    pk.y = packbf(oz, ow);
                    *(uint2*)dst = pk;
                }
            }
        }
        __syncthreads();
    }
}

// ---------------- mma helpers ----------------------------------------------
__device__ __forceinline__ void mma16816(float* c, const unsigned* a, const unsigned* b) {
    asm volatile(
        "mma.sync.aligned.m16n8k16.row.col.f32.bf16.bf16.f32 "
        "{%0,%1,%2,%3}, {%4,%5,%6,%7}, {%8,%9}, {%0,%1,%2,%3};\n"
        : "+f"(c[0]), "+f"(c[1]), "+f"(c[2]), "+f"(c[3])
        : "r"(a[0]), "r"(a[1]), "r"(a[2]), "r"(a[3]), "r"(b[0]), "r"(b[1]));
}
__device__ __forceinline__ void ldsm4(unsigned& r0, unsigned& r1, unsigned& r2,
                                      unsigned& r3, uint32_t a) {
    asm volatile("ldmatrix.sync.aligned.m8n8.x4.shared.b16 {%0,%1,%2,%3}, [%4];\n"
                 : "=r"(r0), "=r"(r1), "=r"(r2), "=r"(r3) : "r"(a));
}
__device__ __forceinline__ void ldsm2(unsigned& r0, unsigned& r1, uint32_t a) {
    asm volatile("ldmatrix.sync.aligned.m8n8.x2.shared.b16 {%0,%1}, [%2];\n"
                 : "=r"(r0), "=r"(r1) : "r"(a));
}
__device__ __forceinline__ void cpa16(uint32_t s, const void* g) {
    asm volatile("cp.async.cg.shared.global [%0], [%1], 16;\n" :: "r"(s), "l"(g) : "memory");
}
template <int N>
__device__ __forceinline__ void cp_wait() {
    asm volatile("cp.async.wait_group %0;\n" :: "n"(N) : "memory");
}

// ---------------- attention: mma.sync bf16, block per (win, head) ----------
__device__ __forceinline__ int swin_reg(int x) { return (x < 120) ? 0 : ((x < 124) ? 1 : 2); }

__global__ __launch_bounds__(128) void attn_kernel() {
    __shared__ __align__(16) __nv_bfloat16 Qs[64 * 40];
    __shared__ __align__(16) __nv_bfloat16 Ks[64 * 40];
    __shared__ __align__(16) __nv_bfloat16 VT[32 * 72];
    int tid = threadIdx.x;
    int hd = blockIdx.x, win = blockIdx.y;
    int widx = win & 255, wh = widx >> 4, ww = widx & 15;
    int warp = tid >> 5, lane = tid & 31;

    const uint4* qg = (const uint4*)(g_qb + (size_t)(win * 12 + hd) * 2048);
    const uint4* kg = (const uint4*)(g_kb + (size_t)(win * 12 + hd) * 2048);
    const uint4* vg = (const uint4*)(g_vb + (size_t)(win * 12 + hd) * 2048);
    for (int i = tid; i < 256; i += 128) {
        int row = i >> 2, q = i & 3;
        *(uint4*)(Qs + row * 40 + q * 8) = qg[i];
        *(uint4*)(Ks + row * 40 + q * 8) = kg[i];
        uint4 v = vg[i];
        const __nv_bfloat16* vb = (const __nv_bfloat16*)&v;
        int d0 = q * 8;
#pragma unroll
        for (int j = 0; j < 8; j++) VT[(d0 + j) * 72 + row] = vb[j];
    }
    __syncthreads();

    uint32_t qb = (uint32_t)__cvta_generic_to_shared(Qs);
    uint32_t kb = (uint32_t)__cvta_generic_to_shared(Ks);
    uint32_t vtb = (uint32_t)__cvta_generic_to_shared(VT);
    int gid = lane >> 2, tq = lane & 3;
    int lrA = ((lane >> 3) & 1) * 8 + (lane & 7);
    int lcA = (lane >> 4) * 8;
    int lrB = lane & 7;
    int lcB = ((lane >> 3) & 1) * 8;
    int m0 = warp * 16;

    // ---- S = Q @ K^T  (16 rows per warp) ----
    unsigned aQ[2][4];
#pragma unroll
    for (int ks = 0; ks < 2; ks++)
        ldsm4(aQ[ks][0], aQ[ks][1], aQ[ks][2], aQ[ks][3],
              qb + (unsigned)(((m0 + lrA) * 40 + ks * 16 + lcA) * 2));
    float sc[8][4];
#pragma unroll
    for (int nt = 0; nt < 8; nt++)
#pragma unroll
        for (int u = 0; u < 4; u++) sc[nt][u] = 0.f;
#pragma unroll
    for (int nt = 0; nt < 8; nt++) {
#pragma unroll
        for (int ks = 0; ks < 2; ks++) {
            unsigned b[2];
            ldsm2(b[0], b[1], kb + (unsigned)(((nt * 8 + lrB) * 40 + ks * 16 + lcB) * 2));
            mma16816(sc[nt], aQ[ks], b);
        }
    }

    // ---- mask + softmax (rows r0=m0+gid, r1=r0+8) ----
    int r0 = m0 + gid, r1 = r0 + 8;
    bool boundary = (wh == 15) || (ww == 15);
    if (boundary) {
        int l0 = swin_reg(wh * 8 + (r0 >> 3)) * 3 + swin_reg(ww * 8 + (r0 & 7));
        int l1 = swin_reg(wh * 8 + (r1 >> 3)) * 3 + swin_reg(ww * 8 + (r1 & 7));
#pragma unroll
        for (int nt = 0; nt < 8; nt++) {
#pragma unroll
            for (int j = 0; j < 2; j++) {
                int col = nt * 8 + tq * 2 + j;
                int lc = swin_reg(wh * 8 + (col >> 3)) * 3 + swin_reg(ww * 8 + (col & 7));
                if (lc != l0) sc[nt][j] -= 100.f;
                if (lc != l1) sc[nt][2 + j] -= 100.f;
            }
        }
    }
    float mx0 = -1e30f, mx1 = -1e30f;
#pragma unroll
    for (int nt = 0; nt < 8; nt++) {
        mx0 = fmaxf(mx0, fmaxf(sc[nt][0], sc[nt][1]));
        mx1 = fmaxf(mx1, fmaxf(sc[nt][2], sc[nt][3]));
    }
#pragma unroll
    for (int o = 1; o <= 2; o <<= 1) {
        mx0 = fmaxf(mx0, __shfl_xor_sync(0xffffffffu, mx0, o));
        mx1 = fmaxf(mx1, __shfl_xor_sync(0xffffffffu, mx1, o));
    }
    float s0 = 0.f, s1 = 0.f;
#pragma unroll
    for (int nt = 0; nt < 8; nt++) {
        sc[nt][0] = __expf(sc[nt][0] - mx0); s0 += sc[nt][0];
        sc[nt][1] = __expf(sc[nt][1] - mx0); s0 += sc[nt][1];
        sc[nt][2] = __expf(sc[nt][2] - mx1); s1 += sc[nt][2];
        sc[nt][3] = __expf(sc[nt][3] - mx1); s1 += sc[nt][3];
    }
#pragma unroll
    for (int o = 1; o <= 2; o <<= 1) {
        s0 += __shfl_xor_sync(0xffffffffu, s0, o);
        s1 += __shfl_xor_sync(0xffffffffu, s1, o);
    }
    float inv0 = 1.f / s0, inv1 = 1.f / s1;

    // ---- P (A-fragments) ----
    unsigned aP[4][4];
#pragma unroll
    for (int kc = 0; kc < 4; kc++) {
        aP[kc][0] = packbf(sc[2 * kc][0] * inv0, sc[2 * kc][1] * inv0);
        aP[kc][1] = packbf(sc[2 * kc][2] * inv1, sc[2 * kc][3] * inv1);
        aP[kc][2] = packbf(sc[2 * kc + 1][0] * inv0, sc[2 * kc + 1][1] * inv0);
        aP[kc][3] = packbf(sc[2 * kc + 1][2] * inv1, sc[2 * kc + 1][3] * inv1);
    }

    // ---- O = P @ V ----
    float av[4][4];
#pragma unroll
    for (int nj = 0; nj < 4; nj++)
#pragma unroll
        for (int u = 0; u < 4; u++) av[nj][u] = 0.f;
#pragma unroll
    for (int nj = 0; nj < 4; nj++) {
#pragma unroll
        for (int kc = 0; kc < 4; kc++) {
            unsigned b[2];
            ldsm2(b[0], b[1], vtb + (unsigned)(((nj * 8 + lrB) * 72 + kc * 16 + lcB) * 2));
            mma16816(av[nj], aP[kc], b);
        }
    }

    // ---- write O (bf16, token-major for proj) ----
    __nv_bfloat16* dst0 = g_aob + ((size_t)(win * 64 + r0)) * 384 + hd * 32;
    __nv_bfloat16* dst1 = g_aob + ((size_t)(win * 64 + r1)) * 384 + hd * 32;
#pragma unroll
    for (int nj = 0; nj < 4; nj++) {
        *(unsigned*)(dst0 + nj * 8 + tq * 2) = packbf(av[nj][0], av[nj][1]);
        *(unsigned*)(dst1 + nj * 8 + tq * 2) = packbf(av[nj][2], av[nj][3]);
    }
}

// ---------------- proj: dwconv3x3 + GELU + unshift + residual --------------
// writes fp32 g_x1 (residual) and bf16 g_x1b (dwconv7 input)
__global__ __launch_bounds__(256) void proj_kernel(const float* __restrict__ wproj,
                                                   const float* __restrict__ x_in) {
    __shared__ float ws[3456];
    int tid = threadIdx.x;
    int win = blockIdx.x;
    int b = win >> 8, widx = win & 255, wh = widx >> 4, ww = widx & 15;

    for (int i = tid; i < 3456; i += 256) ws[i] = wproj[i];
    __syncthreads();

    const uint2* src = (const uint2*)g_aob + (size_t)(win * 64) * 96;
    const float4* ws4 = (const float4*)ws;
    for (int it = tid; it < 6144; it += 256) {
        int t = it / 96, c4 = it - t * 96;
        int r = t >> 3, cc = t & 7;
        float4 acc = {0.f, 0.f, 0.f, 0.f};
#pragma unroll
        for (int dr = 0; dr < 3; dr++) {
            int rr = r + dr - 1;
            if (rr < 0 || rr > 7) continue;
#pragma unroll
            for (int dc = 0; dc < 3; dc++) {
                int c2 = cc + dc - 1;
                if (c2 < 0 || c2 > 7) continue;
                uint2 xv2 = __ldg(src + (rr * 8 + c2) * 96 + c4);
                float2 f01 = __bfloat1622float2(*(__nv_bfloat162*)&xv2.x);
                float2 f23 = __bfloat1622float2(*(__nv_bfloat162*)&xv2.y);
                float4 wv4 = ws4[(dr * 3 + dc) * 96 + c4];
                acc.x += f01.x * wv4.x; acc.y += f01.y * wv4.y;
                acc.z += f23.x * wv4.z; acc.w += f23.y * wv4.w;
            }
        }
        int h = (wh * 8 + r + 4) & 127;
        int w = (ww * 8 + cc + 4) & 127;
        size_t gi = (size_t)(b * 16384 + h * 128 + w) * 96 + c4;
        float4 xv = ((const float4*)x_in)[gi];
        float4 o;
        o.x = xv.x + gelu_exact(acc.x);
        o.y = xv.y + gelu_exact(acc.y);
        o.z = xv.z + gelu_exact(acc.z);
        o.w = xv.w + gelu_exact(acc.w);
        ((float4*)g_x1)[gi] = o;
        uint2 pk;
        pk.x = packbf(o.x, o.y);
        pk.y = packbf(o.z, o.w);
        ((uint2*)g_x1b)[gi] = pk;
    }
}

// ---------------- 7x7 depthwise conv + bias (bf16 in, bf16 out) ------------
__global__ __launch_bounds__(256) void dwconv7_kernel(const float* __restrict__ w7,
                                                      const float* __restrict__ bias) {
    int idx = blockIdx.x * 256 + threadIdx.x;    // 1,572,864 threads
    int c4 = idx % 96;
    int t4 = idx / 96;                           // 0..16383
    int b = t4 >> 12, rem = t4 & 4095;
    int h = rem >> 5, w0 = (rem & 31) * 4;
    const uint2* x2 = (const uint2*)g_x1b;
    const float4* wp4 = (const float4*)w7;
    float4 bz = ((const float4*)bias)[c4];
    float4 acc[4] = {bz, bz, bz, bz};
#pragma unroll
    for (int dr = 0; dr < 7; dr++) {
        int hh = h + dr - 3;
        if ((unsigned)hh >= 128u) continue;
        float4 wt[7];
#pragma unroll
        for (int dc = 0; dc < 7; dc++) wt[dc] = wp4[(dr * 7 + dc) * 96 + c4];
        const uint2* rowp = x2 + (size_t)((b << 14) + (hh << 7)) * 96 + c4;
#pragma unroll
        for (int j = 0; j < 10; j++) {
            int c = w0 + j - 3;
            if ((unsigned)c >= 128u) continue;
            uint2 xv2 = __ldg(rowp + (size_t)c * 96);
            float2 f01 = __bfloat1622float2(*(__nv_bfloat162*)&xv2.x);
            float2 f23 = __bfloat1622float2(*(__nv_bfloat162*)&xv2.y);
#pragma unroll
            for (int o = 0; o < 4; o++) {
                int tap = j - o;
                if (tap >= 0 && tap < 7) {
                    acc[o].x += f01.x * wt[tap].x; acc[o].y += f01.y * wt[tap].y;
                    acc[o].z += f23.x * wt[tap].z; acc[o].w += f23.y * wt[tap].w;
                }
            }
        }
    }
#pragma unroll
    for (int o = 0; o < 4; o++) {
        int token = (b << 14) + (h << 7) + w0 + o;
        uint2 pk;
        pk.x = packbf(acc[o].x, acc[o].y);
        pk.y = packbf(acc[o].z, acc[o].w);
        ((uint2*)g_m0b)[(size_t)token * 96 + c4] = pk;
    }
}

// ---------------- weight prep: transpose + bf16 ----------------------------
__global__ void prep_kernel(const float* __restrict__ pw1, const float* __restrict__ pw2) {
    int i = blockIdx.x * 256 + threadIdx.x;
    if (i < 589824) {
        int n = i / 384, k = i - n * 384;
        g_w1t[i] = __float2bfloat16(pw1[k * 1536 + n]);
        int n2 = i / 1536, k2 = i - n2 * 1536;
        g_w2t[i] = __float2bfloat16(pw2[k2 * 384 + n2]);
    }
}

// ---------------- bf16 GEMM: 3-stage cp.async + ldmatrix + mma.sync --------
#define GBM 128
#define GBN 128
#define GBK 32
#define GST 40
#define GS_MAT (GBM * GST * 2)
#define GS_STAGE (2 * GS_MAT)
#define GS_TOT (3 * GS_STAGE)

template <int KG, bool GELU_EPI>
__global__ __launch_bounds__(256) void gemm_kernel(
    const __nv_bfloat16* __restrict__ A, const __nv_bfloat16* __restrict__ Bt,
    const float* __restrict__ bias, const float* __restrict__ gamma,
    const float* __restrict__ resid, __nv_bfloat16* __restrict__ outB,
    float* __restrict__ outF, int NG) {
    uint32_t sbase = (uint32_t)__cvta_generic_to_shared(dyn_smem);

    int tid = threadIdx.x;
    int bm = blockIdx.x * GBM, bn = blockIdx.y * GBN;
    int warp = tid >> 5, lane = tid & 31;
    int wm = (warp >> 2) * 64;
    int wn = (warp & 3) * 32;
    int gid = lane >> 2, tq = lane & 3;
    int lrA = ((lane >> 3) & 1) * 8 + (lane & 7);
    int lcA = (lane >> 4) * 8;
    int lrB = lane & 7;
    int lcB = ((lane >> 3) & 1) * 8;

    float acc[4][4][4];
#pragma unroll
    for (int mi = 0; mi < 4; mi++)
#pragma unroll
        for (int ni = 0; ni < 4; ni++)
#pragma unroll
            for (int u = 0; u < 4; u++) acc[mi][ni][u] = 0.f;

    auto load_tile = [&](int kc, int s) {
        unsigned base = sbase + (unsigned)s * GS_STAGE;
#pragma unroll
        for (int it = tid; it < 512; it += 256) {
            int row = it >> 2, q = it & 3;
            unsigned so = (unsigned)((row * GST + q * 8) * 2);
            cpa16(base + so, A + (size_t)(bm + row) * KG + kc + q * 8);
            cpa16(base + GS_MAT + so, Bt + (size_t)(bn + row) * KG + kc + q * 8);
        }
        asm volatile("cp.async.commit_group;\n" ::: "memory");
    };

    constexpr int NIT = KG / GBK;
    load_tile(0, 0);
    load_tile(GBK, 1);
    int sidx = 0;
    for (int i = 0; i < NIT; i++) {
        cp_wait<1>();
        __syncthreads();
        if (i + 2 < NIT) load_tile((i + 2) * GBK, (i + 2) % 3);
        unsigned abase = sbase + (unsigned)sidx * GS_STAGE;
        unsigned bbase = abase + GS_MAT;
#pragma unroll
        for (int ks = 0; ks < 2; ks++) {
            int k0 = ks * 16;
            unsigned av[4][4], bv[4][2];
#pragma unroll
            for (int mi = 0; mi < 4; mi++)
                ldsm4(av[mi][0], av[mi][1], av[mi][2], av[mi][3],
                      abase + (unsigned)(((wm + mi * 16 + lrA) * GST + k0 + lcA) * 2));
#pragma unroll
            for (int ni = 0; ni < 4; ni++)
                ldsm2(bv[ni][0], bv[ni][1],
                      bbase + (unsigned)(((wn + ni * 8 + lrB) * GST + k0 + lcB) * 2));
#pragma unroll
            for (int mi = 0; mi < 4; mi++)
#pragma unroll
                for (int ni = 0; ni < 4; ni++) mma16816(acc[mi][ni], av[mi], bv[ni]);
        }
        sidx = (sidx + 1) % 3;
    }

#pragma unroll
    for (int mi = 0; mi < 4; mi++) {
        int r0 = bm + wm + mi * 16 + gid;
#pragma unroll
        for (int ni = 0; ni < 4; ni++) {
            int c0 = bn + wn + ni * 8 + tq * 2;
            float* a4 = acc[mi][ni];
            if (GELU_EPI) {
                float b0 = bias[c0], b1 = bias[c0 + 1];
                __nv_bfloat162 v0, v1;
                v0.x = __float2bfloat16(gelu_exact(a4[0] + b0));
                v0.y = __float2bfloat16(gelu_exact(a4[1] + b1));
                v1.x = __float2bfloat16(gelu_exact(a4[2] + b0));
                v1.y = __float2bfloat16(gelu_exact(a4[3] + b1));
                *(__nv_bfloat162*)(outB + (size_t)r0 * NG + c0) = v0;
                *(__nv_bfloat162*)(outB + (size_t)(r0 + 8) * NG + c0) = v1;
            } else {
                float b0 = bias[c0], b1 = bias[c0 + 1];
                float g0 = gamma[c0], g1 = gamma[c0 + 1];
                size_t o0 = (size_t)r0 * NG + c0;
                size_t o1 = (size_t)(r0 + 8) * NG + c0;
                float2 r0v = *(const float2*)(resid + o0);
                float2 r1v = *(const float2*)(resid + o1);
                float2 ov0 = {r0v.x + g0 * (a4[0] + b0), r0v.y + g1 * (a4[1] + b1)};
                float2 ov1 = {r1v.x + g0 * (a4[2] + b0), r1v.y + g1 * (a4[3] + b1)};
                *(float2*)(outF + o0) = ov0;
                *(float2*)(outF + o1) = ov1;
            }
        }
    }
}

// ---------------------------------------------------------------------------
extern "C" void kernel_launch(void* const* d_in, const int* in_sizes, int n_in,
                              void* d_out, int out_size) {
    (void)in_sizes; (void)n_in; (void)out_size;
    const float* x     = (const float*)d_in[0];
    const float* n1g   = (const float*)d_in[1];
    const float* n1b   = (const float*)d_in[2];
    const float* wq    = (const float*)d_in[3];
    const float* lnqg  = (const float*)d_in[4];
    const float* lnqb  = (const float*)d_in[5];
    const float* wk    = (const float*)d_in[6];
    const float* lnkg  = (const float*)d_in[7];
    const float* lnkb  = (const float*)d_in[8];
    const float* wv    = (const float*)d_in[9];
    const float* lnvg  = (const float*)d_in[10];
    const float* lnvb  = (const float*)d_in[11];
    const float* wproj = (const float*)d_in[12];
    const float* dw_w  = (const float*)d_in[13];
    const float* dw_b  = (const float*)d_in[14];
    const float* mng   = (const float*)d_in[15];
    const float* mnb   = (const float*)d_in[16];
    const float* pw1   = (const float*)d_in[17];
    const float* pw1b  = (const float*)d_in[18];
    const float* pw2   = (const float*)d_in[19];
    const float* pw2b  = (const float*)d_in[20];
    const float* gam   = (const float*)d_in[21];
    float* out = (float*)d_out;

    float *x1;
    __nv_bfloat16 *m0b, *m1, *hbuf, *w1t, *w2t;
    cudaGetSymbolAddress((void**)&m0b, g_m0b);
    cudaGetSymbolAddress((void**)&x1, g_x1);
    cudaGetSymbolAddress((void**)&m1, g_m1);
    cudaGetSymbolAddress((void**)&hbuf, g_h);
    cudaGetSymbolAddress((void**)&w1t, g_w1t);
    cudaGetSymbolAddress((void**)&w2t, g_w2t);

    cudaFuncSetAttribute(qkv_kernel, cudaFuncAttributeMaxDynamicSharedMemorySize, 62976);
    cudaFuncSetAttribute(gemm_kernel<384, true>,
                         cudaFuncAttributeMaxDynamicSharedMemorySize, GS_TOT);
    cudaFuncSetAttribute(gemm_kernel<1536, false>,
                         cudaFuncAttributeMaxDynamicSharedMemorySize, GS_TOT);

    // 1. QKV (LN1 fused in regs, bf16 window, pairwise conv)
    qkv_kernel<<<NWIN, 256, 62976>>>(x, n1g, n1b, wq, lnqg, lnqb,
                                     wk, lnkg, lnkb, wv, lnvg, lnvb);
    // 2. attention (mma.sync bf16, bf16 out)
    attn_kernel<<<dim3(12, NWIN), 128>>>();
    // 3. proj + residual (bf16 in, fp32 + bf16 out)
    proj_kernel<<<NWIN, 256>>>(wproj, x);
    // 4. 7x7 depthwise (bf16 in/out)
    dwconv7_kernel<<<6144, 256>>>(dw_w, dw_b);
    // 5. LN bf16 -> bf16
    ln_bf_kernel<<<8192, 256>>>(m0b, m1, mng, mnb, 1e-6f);
    // 6. weight prep
    prep_kernel<<<2304, 256>>>(pw1, pw2);
    // 7. GEMM1 + GELU
    gemm_kernel<384, true><<<dim3(512, 12), 256, GS_TOT>>>(m1, w1t, pw1b, nullptr,
                                                           nullptr, hbuf, nullptr, 1536);
    // 8. GEMM2 + gamma + residual
    gemm_kernel<1536, false><<<dim3(512, 3), 256, GS_TOT>>>(hbuf, w2t, pw2b, gam, x1,
                                                            nullptr, out, 384);
}

// round 14
// speedup vs baseline: 1.0274x; 1.0274x over previous
#include <cuda_runtime.h>
#include <cuda_bf16.h>
#include <cstdint>

// ---------------------------------------------------------------------------
// ConvSwinTransformerBlock  (B=4, H=W=128, C=384, WS=8, SHIFT=4, HEADS=12)
// R14: revert R13 (bf16 dwconv7 input hurt: cvt made it issue-bound).
//      Base = R12; dwconv7 widened to 1h x 8w per thread (fp32 in, fewer LDG).
// ---------------------------------------------------------------------------

#define CC 384
#define NWIN 1024             // 4 * 256

extern __shared__ char dyn_smem[];

// ---------------- scratch (device globals: allocation-guard safe) ----------
__device__ __nv_bfloat16 g_qb [25165824];       // [win*12+hd][64][32]
__device__ __nv_bfloat16 g_kb [25165824];
__device__ __nv_bfloat16 g_vb [25165824];
__device__ __nv_bfloat16 g_aob[25165824];       // attn out, bf16
__device__ float g_x1 [25165824];               // fp32 (residual + dwconv7 in)
__device__ __nv_bfloat16 g_m0b[25165824];       // dwconv7 out, bf16
__device__ __nv_bfloat16 g_m1 [25165824];
__device__ __nv_bfloat16 g_h  [100663296];      // 65536 x 1536
__device__ __nv_bfloat16 g_w1t[589824];         // [1536][384]
__device__ __nv_bfloat16 g_w2t[589824];         // [384][1536]

__device__ __forceinline__ float gelu_exact(float x) {
    return 0.5f * x * (1.0f + erff(x * 0.7071067811865476f));
}
__device__ __forceinline__ unsigned packbf(float a, float b) {
    __nv_bfloat162 v = __floats2bfloat162_rn(a, b);
    return *(unsigned*)&v;
}

// ---------------- LayerNorm bf16->bf16 over C=384 (warp per token) ---------
__global__ void ln_bf_kernel(const __nv_bfloat16* __restrict__ in,
                             __nv_bfloat16* __restrict__ out,
                             const float* __restrict__ g,
                             const float* __restrict__ bta, float eps) {
    int token = blockIdx.x * 8 + (threadIdx.x >> 5);
    int lane = threadIdx.x & 31;
    const __nv_bfloat162* p = (const __nv_bfloat162*)(in + (size_t)token * CC);
    float2 v[6];
    float s = 0.f, s2 = 0.f;
#pragma unroll
    for (int i = 0; i < 6; i++) {
        v[i] = __bfloat1622float2(p[lane + 32 * i]);
        s += v[i].x + v[i].y;
        s2 += v[i].x * v[i].x + v[i].y * v[i].y;
    }
#pragma unroll
    for (int o = 16; o; o >>= 1) {
        s += __shfl_xor_sync(0xffffffffu, s, o);
        s2 += __shfl_xor_sync(0xffffffffu, s2, o);
    }
    float mu = s * (1.f / 384.f);
    float var = s2 * (1.f / 384.f) - mu * mu;
    float rstd = rsqrtf(var + eps);
    __nv_bfloat162* q = (__nv_bfloat162*)(out + (size_t)token * CC);
    const float2* g2 = (const float2*)g;
    const float2* b2 = (const float2*)bta;
#pragma unroll
    for (int i = 0; i < 6; i++) {
        int j = lane + 32 * i;
        float2 gg = g2[j], bb = b2[j];
        q[j] = __floats2bfloat162_rn((v[i].x - mu) * rstd * gg.x + bb.x,
                                     (v[i].y - mu) * rstd * gg.y + bb.y);
    }
}

// ---------------- QKV: LN1(reg) -> bf16 window -> dwconv3x3 -> LN ----------
// smem: xs (64*384 bf16 = 49152 B) + ws (3456 f32 = 13824 B) = 62976 B
__global__ __launch_bounds__(256) void qkv_kernel(
    const float* __restrict__ x, const float* __restrict__ n1g,
    const float* __restrict__ n1b,
    const float* __restrict__ wq, const float* __restrict__ lnqg,
    const float* __restrict__ lnqb,
    const float* __restrict__ wk, const float* __restrict__ lnkg,
    const float* __restrict__ lnkb,
    const float* __restrict__ wv, const float* __restrict__ lnvg,
    const float* __restrict__ lnvb) {
    __nv_bfloat16* xs = (__nv_bfloat16*)dyn_smem;          // 64*384 bf16
    float* ws = (float*)(dyn_smem + 49152);                // 3456 floats
    uint2* xs_u2 = (uint2*)xs;                             // 96 uint2 per token
    int tid = threadIdx.x;
    int win = blockIdx.x;
    int b = win >> 8, widx = win & 255, wh = widx >> 4, ww = widx & 15;
    int warp = tid >> 5, lane = tid & 31;

    // ---- phase 1: load + LN1 in registers, write bf16 window ----
    for (int t = warp; t < 64; t += 8) {
        int r = t >> 3, cc0 = t & 7;
        int h = (wh * 8 + r + 4) & 127;
        int w = (ww * 8 + cc0 + 4) & 127;
        const float4* src = (const float4*)x + (size_t)(b * 16384 + h * 128 + w) * 96;
        float4 xv[3];
        float s = 0.f, s2 = 0.f;
#pragma unroll
        for (int g = 0; g < 3; g++) {
            xv[g] = __ldg(src + g * 32 + lane);
            s += xv[g].x + xv[g].y + xv[g].z + xv[g].w;
            s2 += xv[g].x * xv[g].x + xv[g].y * xv[g].y +
                  xv[g].z * xv[g].z + xv[g].w * xv[g].w;
        }
#pragma unroll
        for (int o = 16; o; o >>= 1) {
            s += __shfl_xor_sync(0xffffffffu, s, o);
            s2 += __shfl_xor_sync(0xffffffffu, s2, o);
        }
        float mu = s * (1.f / 384.f);
        float var = s2 * (1.f / 384.f) - mu * mu;
        float rstd = rsqrtf(var + 1e-5f);
#pragma unroll
        for (int g = 0; g < 3; g++) {
            int c4 = g * 32 + lane;
            float4 g4 = ((const float4*)n1g)[c4];
            float4 b4 = ((const float4*)n1b)[c4];
            float ox = (xv[g].x - mu) * rstd * g4.x + b4.x;
            float oy = (xv[g].y - mu) * rstd * g4.y + b4.y;
            float oz = (xv[g].z - mu) * rstd * g4.z + b4.z;
            float ow = (xv[g].w - mu) * rstd * g4.w + b4.w;
            uint2 pk;
            pk.x = packbf(ox, oy);
            pk.y = packbf(oz, ow);
            xs_u2[t * 96 + c4] = pk;
        }
    }
    __syncthreads();

    const float* Wp[3] = {wq, wk, wv};
    const float* Gg[3] = {lnqg, lnkg, lnvg};
    const float* Bb[3] = {lnqb, lnkb, lnvb};
    __nv_bfloat16* Out[3] = {g_qb, g_kb, g_vb};
    const float4* ws4 = (const float4*)ws;
    int cc = warp;   // column this warp owns

    for (int p = 0; p < 3; p++) {
        for (int i = tid; i < 3456; i += 256) ws[i] = Wp[p][i];
        __syncthreads();
        float scale = (p == 0) ? 0.17677669529663687f : 1.0f;  // 1/sqrt(32)

        for (int m = 0; m < 4; m++) {
            int rA = 2 * m;                    // token rows rA, rA+1
            float4 a0[3], a1[3];
#pragma unroll
            for (int g = 0; g < 3; g++) {
                a0[g] = make_float4(0.f, 0.f, 0.f, 0.f);
                a1[g] = make_float4(0.f, 0.f, 0.f, 0.f);
            }
            {
                float4 wcur[9], wprev[9];      // scoped: freed before LN
#pragma unroll
                for (int dr2 = 0; dr2 < 4; dr2++) {
                    if (dr2 > 0) {
#pragma unroll
                        for (int i = 0; i < 9; i++) wprev[i] = wcur[i];
                    }
                    if (dr2 <= 2) {
#pragma unroll
                        for (int dc = 0; dc < 3; dc++)
#pragma unroll
                            for (int g = 0; g < 3; g++)
                                wcur[dc * 3 + g] = ws4[(dr2 * 3 + dc) * 96 + g * 32 + lane];
                    }
                    int rr = rA - 1 + dr2;
                    if (rr < 0 || rr > 7) continue;
                    bool u0 = (dr2 <= 2);      // token row rA uses tap row dr2
                    bool u1 = (dr2 >= 1);      // token row rA+1 uses tap row dr2-1
#pragma unroll
                    for (int dc = 0; dc < 3; dc++) {
                        int c2 = cc + dc - 1;
                        if (c2 < 0 || c2 > 7) continue;
#pragma unroll
                        for (int g = 0; g < 3; g++) {
                            uint2 xv2 = xs_u2[(rr * 8 + c2) * 96 + g * 32 + lane];
                            float2 f01 = __bfloat1622float2(*(__nv_bfloat162*)&xv2.x);
                            float2 f23 = __bfloat1622float2(*(__nv_bfloat162*)&xv2.y);
                            if (u0) {
                                float4 w = wcur[dc * 3 + g];
                                a0[g].x += f01.x * w.x; a0[g].y += f01.y * w.y;
                                a0[g].z += f23.x * w.z; a0[g].w += f23.y * w.w;
                            }
                            if (u1) {
                                float4 w = wprev[dc * 3 + g];
                                a1[g].x += f01.x * w.x; a1[g].y += f01.y * w.y;
                                a1[g].z += f23.x * w.z; a1[g].w += f23.y * w.w;
                            }
                        }
                    }
                }
            }
            // ---- LN + store for the two tokens (fused sum/sumsq) ----
#pragma unroll
            for (int half = 0; half < 2; half++) {
                float4* vv = half ? a1 : a0;
                int t = (rA + half) * 8 + cc;
                float s = 0.f, s2 = 0.f;
#pragma unroll
                for (int g = 0; g < 3; g++) {
                    s += vv[g].x + vv[g].y + vv[g].z + vv[g].w;
                    s2 += vv[g].x * vv[g].x + vv[g].y * vv[g].y +
                          vv[g].z * vv[g].z + vv[g].w * vv[g].w;
                }
#pragma unroll
                for (int o = 16; o; o >>= 1) {
                    s += __shfl_xor_sync(0xffffffffu, s, o);
                    s2 += __shfl_xor_sync(0xffffffffu, s2, o);
                }
                float mu = s * (1.f / 384.f);
                float var = s2 * (1.f / 384.f) - mu * mu;
                float rstd = rsqrtf(var + 1e-5f);
#pragma unroll
                for (int g = 0; g < 3; g++) {
                    int c4 = g * 32 + lane;
                    float4 g4 = ((const float4*)Gg[p])[c4];
                    float4 b4 = ((const float4*)Bb[p])[c4];
                    float ox = ((vv[g].x - mu) * rstd * g4.x + b4.x) * scale;
                    float oy = ((vv[g].y - mu) * rstd * g4.y + b4.y) * scale;
                    float oz = ((vv[g].z - mu) * rstd * g4.z + b4.z) * scale;
                    float ow = ((vv[g].w - mu) * rstd * g4.w + b4.w) * scale;
                    int head = c4 >> 3, d0 = (c4 & 7) * 4;
                    __nv_bfloat16* dst = Out[p] +
                        ((size_t)(win * 12 + head) * 64 + t) * 32 + d0;
                    uint2 pk;
                    pk.x = packbf(ox, oy);
                    pk.y = packbf(oz, ow);
                    *(uint2*)dst = pk;
                }
            }
        }
        __syncthreads();
    }
}

// ---------------- mma helpers ----------------------------------------------
__device__ __forceinline__ void mma16816(float* c, const unsigned* a, const unsigned* b) {
    asm volatile(
        "mma.sync.aligned.m16n8k16.row.col.f32.bf16.bf16.f32 "
        "{%0,%1,%2,%3}, {%4,%5,%6,%7}, {%8,%9}, {%0,%1,%2,%3};\n"
        : "+f"(c[0]), "+f"(c[1]), "+f"(c[2]), "+f"(c[3])
        : "r"(a[0]), "r"(a[1]), "r"(a[2]), "r"(a[3]), "r"(b[0]), "r"(b[1]));
}
__device__ __forceinline__ void ldsm4(unsigned& r0, unsigned& r1, unsigned& r2,
                                      unsigned& r3, uint32_t a) {
    asm volatile("ldmatrix.sync.aligned.m8n8.x4.shared.b16 {%0,%1,%2,%3}, [%4];\n"
                 : "=r"(r0), "=r"(r1), "=r"(r2), "=r"(r3) : "r"(a));
}
__device__ __forceinline__ void ldsm2(unsigned& r0, unsigned& r1, uint32_t a) {
    asm volatile("ldmatrix.sync.aligned.m8n8.x2.shared.b16 {%0,%1}, [%2];\n"
                 : "=r"(r0), "=r"(r1) : "r"(a));
}
__device__ __forceinline__ void cpa16(uint32_t s, const void* g) {
    asm volatile("cp.async.cg.shared.global [%0], [%1], 16;\n" :: "r"(s), "l"(g) : "memory");
}
template <int N>
__device__ __forceinline__ void cp_wait() {
    asm volatile("cp.async.wait_group %0;\n" :: "n"(N) : "memory");
}

// ---------------- attention: mma.sync bf16, block per (win, head) ----------
__device__ __forceinline__ int swin_reg(int x) { return (x < 120) ? 0 : ((x < 124) ? 1 : 2); }

__global__ __launch_bounds__(128) void attn_kernel() {
    __shared__ __align__(16) __nv_bfloat16 Qs[64 * 40];
    __shared__ __align__(16) __nv_bfloat16 Ks[64 * 40];
    __shared__ __align__(16) __nv_bfloat16 VT[32 * 72];
    int tid = threadIdx.x;
    int hd = blockIdx.x, win = blockIdx.y;
    int widx = win & 255, wh = widx >> 4, ww = widx & 15;
    int warp = tid >> 5, lane = tid & 31;

    const uint4* qg = (const uint4*)(g_qb + (size_t)(win * 12 + hd) * 2048);
    const uint4* kg = (const uint4*)(g_kb + (size_t)(win * 12 + hd) * 2048);
    const uint4* vg = (const uint4*)(g_vb + (size_t)(win * 12 + hd) * 2048);
    for (int i = tid; i < 256; i += 128) {
        int row = i >> 2, q = i & 3;
        *(uint4*)(Qs + row * 40 + q * 8) = qg[i];
        *(uint4*)(Ks + row * 40 + q * 8) = kg[i];
        uint4 v = vg[i];
        const __nv_bfloat16* vb = (const __nv_bfloat16*)&v;
        int d0 = q * 8;
#pragma unroll
        for (int j = 0; j < 8; j++) VT[(d0 + j) * 72 + row] = vb[j];
    }
    __syncthreads();

    uint32_t qb = (uint32_t)__cvta_generic_to_shared(Qs);
    uint32_t kb = (uint32_t)__cvta_generic_to_shared(Ks);
    uint32_t vtb = (uint32_t)__cvta_generic_to_shared(VT);
    int gid = lane >> 2, tq = lane & 3;
    int lrA = ((lane >> 3) & 1) * 8 + (lane & 7);
    int lcA = (lane >> 4) * 8;
    int lrB = lane & 7;
    int lcB = ((lane >> 3) & 1) * 8;
    int m0 = warp * 16;

    // ---- S = Q @ K^T  (16 rows per warp) ----
    unsigned aQ[2][4];
#pragma unroll
    for (int ks = 0; ks < 2; ks++)
        ldsm4(aQ[ks][0], aQ[ks][1], aQ[ks][2], aQ[ks][3],
              qb + (unsigned)(((m0 + lrA) * 40 + ks * 16 + lcA) * 2));
    float sc[8][4];
#pragma unroll
    for (int nt = 0; nt < 8; nt++)
#pragma unroll
        for (int u = 0; u < 4; u++) sc[nt][u] = 0.f;
#pragma unroll
    for (int nt = 0; nt < 8; nt++) {
#pragma unroll
        for (int ks = 0; ks < 2; ks++) {
            unsigned b[2];
            ldsm2(b[0], b[1], kb + (unsigned)(((nt * 8 + lrB) * 40 + ks * 16 + lcB) * 2));
            mma16816(sc[nt], aQ[ks], b);
        }
    }

    // ---- mask + softmax (rows r0=m0+gid, r1=r0+8) ----
    int r0 = m0 + gid, r1 = r0 + 8;
    bool boundary = (wh == 15) || (ww == 15);
    if (boundary) {
        int l0 = swin_reg(wh * 8 + (r0 >> 3)) * 3 + swin_reg(ww * 8 + (r0 & 7));
        int l1 = swin_reg(wh * 8 + (r1 >> 3)) * 3 + swin_reg(ww * 8 + (r1 & 7));
#pragma unroll
        for (int nt = 0; nt < 8; nt++) {
#pragma unroll
            for (int j = 0; j < 2; j++) {
                int col = nt * 8 + tq * 2 + j;
                int lc = swin_reg(wh * 8 + (col >> 3)) * 3 + swin_reg(ww * 8 + (col & 7));
                if (lc != l0) sc[nt][j] -= 100.f;
                if (lc != l1) sc[nt][2 + j] -= 100.f;
            }
        }
    }
    float mx0 = -1e30f, mx1 = -1e30f;
#pragma unroll
    for (int nt = 0; nt < 8; nt++) {
        mx0 = fmaxf(mx0, fmaxf(sc[nt][0], sc[nt][1]));
        mx1 = fmaxf(mx1, fmaxf(sc[nt][2], sc[nt][3]));
    }
#pragma unroll
    for (int o = 1; o <= 2; o <<= 1) {
        mx0 = fmaxf(mx0, __shfl_xor_sync(0xffffffffu, mx0, o));
        mx1 = fmaxf(mx1, __shfl_xor_sync(0xffffffffu, mx1, o));
    }
    float s0 = 0.f, s1 = 0.f;
#pragma unroll
    for (int nt = 0; nt < 8; nt++) {
        sc[nt][0] = __expf(sc[nt][0] - mx0); s0 += sc[nt][0];
        sc[nt][1] = __expf(sc[nt][1] - mx0); s0 += sc[nt][1];
        sc[nt][2] = __expf(sc[nt][2] - mx1); s1 += sc[nt][2];
        sc[nt][3] = __expf(sc[nt][3] - mx1); s1 += sc[nt][3];
    }
#pragma unroll
    for (int o = 1; o <= 2; o <<= 1) {
        s0 += __shfl_xor_sync(0xffffffffu, s0, o);
        s1 += __shfl_xor_sync(0xffffffffu, s1, o);
    }
    float inv0 = 1.f / s0, inv1 = 1.f / s1;

    // ---- P (A-fragments) ----
    unsigned aP[4][4];
#pragma unroll
    for (int kc = 0; kc < 4; kc++) {
        aP[kc][0] = packbf(sc[2 * kc][0] * inv0, sc[2 * kc][1] * inv0);
        aP[kc][1] = packbf(sc[2 * kc][2] * inv1, sc[2 * kc][3] * inv1);
        aP[kc][2] = packbf(sc[2 * kc + 1][0] * inv0, sc[2 * kc + 1][1] * inv0);
        aP[kc][3] = packbf(sc[2 * kc + 1][2] * inv1, sc[2 * kc + 1][3] * inv1);
    }

    // ---- O = P @ V ----
    float av[4][4];
#pragma unroll
    for (int nj = 0; nj < 4; nj++)
#pragma unroll
        for (int u = 0; u < 4; u++) av[nj][u] = 0.f;
#pragma unroll
    for (int nj = 0; nj < 4; nj++) {
#pragma unroll
        for (int kc = 0; kc < 4; kc++) {
            unsigned b[2];
            ldsm2(b[0], b[1], vtb + (unsigned)(((nj * 8 + lrB) * 72 + kc * 16 + lcB) * 2));
            mma16816(av[nj], aP[kc], b);
        }
    }

    // ---- write O (bf16, token-major for proj) ----
    __nv_bfloat16* dst0 = g_aob + ((size_t)(win * 64 + r0)) * 384 + hd * 32;
    __nv_bfloat16* dst1 = g_aob + ((size_t)(win * 64 + r1)) * 384 + hd * 32;
#pragma unroll
    for (int nj = 0; nj < 4; nj++) {
        *(unsigned*)(dst0 + nj * 8 + tq * 2) = packbf(av[nj][0], av[nj][1]);
        *(unsigned*)(dst1 + nj * 8 + tq * 2) = packbf(av[nj][2], av[nj][3]);
    }
}

// ---------------- proj: dwconv3x3 + GELU + unshift + residual (bf16 in) ----
__global__ __launch_bounds__(256) void proj_kernel(const float* __restrict__ wproj,
                                                   const float* __restrict__ x_in) {
    __shared__ float ws[3456];
    int tid = threadIdx.x;
    int win = blockIdx.x;
    int b = win >> 8, widx = win & 255, wh = widx >> 4, ww = widx & 15;

    for (int i = tid; i < 3456; i += 256) ws[i] = wproj[i];
    __syncthreads();

    const uint2* src = (const uint2*)g_aob + (size_t)(win * 64) * 96;
    const float4* ws4 = (const float4*)ws;
    for (int it = tid; it < 6144; it += 256) {
        int t = it / 96, c4 = it - t * 96;
        int r = t >> 3, cc = t & 7;
        float4 acc = {0.f, 0.f, 0.f, 0.f};
#pragma unroll
        for (int dr = 0; dr < 3; dr++) {
            int rr = r + dr - 1;
            if (rr < 0 || rr > 7) continue;
#pragma unroll
            for (int dc = 0; dc < 3; dc++) {
                int c2 = cc + dc - 1;
                if (c2 < 0 || c2 > 7) continue;
                uint2 xv2 = __ldg(src + (rr * 8 + c2) * 96 + c4);
                float2 f01 = __bfloat1622float2(*(__nv_bfloat162*)&xv2.x);
                float2 f23 = __bfloat1622float2(*(__nv_bfloat162*)&xv2.y);
                float4 wv4 = ws4[(dr * 3 + dc) * 96 + c4];
                acc.x += f01.x * wv4.x; acc.y += f01.y * wv4.y;
                acc.z += f23.x * wv4.z; acc.w += f23.y * wv4.w;
            }
        }
        int h = (wh * 8 + r + 4) & 127;
        int w = (ww * 8 + cc + 4) & 127;
        size_t gi = (size_t)(b * 16384 + h * 128 + w) * 96 + c4;
        float4 xv = ((const float4*)x_in)[gi];
        float4 o;
        o.x = xv.x + gelu_exact(acc.x);
        o.y = xv.y + gelu_exact(acc.y);
        o.z = xv.z + gelu_exact(acc.z);
        o.w = xv.w + gelu_exact(acc.w);
        ((float4*)g_x1)[gi] = o;
    }
}

// ---------------- 7x7 depthwise conv + bias (1h x 8w per thread) -----------
__global__ __launch_bounds__(256) void dwconv7_kernel(const float* __restrict__ w7,
                                                      const float* __restrict__ bias) {
    int idx = blockIdx.x * 256 + threadIdx.x;    // 786,432 threads
    int c4 = idx % 96;
    int t8 = idx / 96;                           // 0..8191
    int b = t8 >> 11, rem = t8 & 2047;
    int h = rem >> 4, w0 = (rem & 15) * 8;
    const float4* x4 = (const float4*)g_x1;
    const float4* wp4 = (const float4*)w7;
    float4 bz = ((const float4*)bias)[c4];
    float4 acc[8] = {bz, bz, bz, bz, bz, bz, bz, bz};
#pragma unroll
    for (int dr = 0; dr < 7; dr++) {
        int hh = h + dr - 3;
        if ((unsigned)hh >= 128u) continue;
        float4 wt[7];
#pragma unroll
        for (int dc = 0; dc < 7; dc++) wt[dc] = wp4[(dr * 7 + dc) * 96 + c4];
        const float4* rowp = x4 + (size_t)((b << 14) + (hh << 7)) * 96 + c4;
#pragma unroll
        for (int j = 0; j < 14; j++) {
            int c = w0 + j - 3;
            if ((unsigned)c >= 128u) continue;
            float4 xv = __ldg(rowp + (size_t)c * 96);
#pragma unroll
            for (int o = 0; o < 8; o++) {
                int tap = j - o;
                if (tap >= 0 && tap < 7) {
                    acc[o].x += xv.x * wt[tap].x; acc[o].y += xv.y * wt[tap].y;
                    acc[o].z += xv.z * wt[tap].z; acc[o].w += xv.w * wt[tap].w;
                }
            }
        }
    }
#pragma unroll
    for (int o = 0; o < 8; o++) {
        int token = (b << 14) + (h << 7) + w0 + o;
        uint2 pk;
        pk.x = packbf(acc[o].x, acc[o].y);
        pk.y = packbf(acc[o].z, acc[o].w);
        ((uint2*)g_m0b)[(size_t)token * 96 + c4] = pk;
    }
}

// ---------------- weight prep: transpose + bf16 ----------------------------
__global__ void prep_kernel(const float* __restrict__ pw1, const float* __restrict__ pw2) {
    int i = blockIdx.x * 256 + threadIdx.x;
    if (i < 589824) {
        int n = i / 384, k = i - n * 384;
        g_w1t[i] = __float2bfloat16(pw1[k * 1536 + n]);
        int n2 = i / 1536, k2 = i - n2 * 1536;
        g_w2t[i] = __float2bfloat16(pw2[k2 * 384 + n2]);
    }
}

// ---------------- bf16 GEMM: 3-stage cp.async + ldmatrix + mma.sync --------
#define GBM 128
#define GBN 128
#define GBK 32
#define GST 40
#define GS_MAT (GBM * GST * 2)
#define GS_STAGE (2 * GS_MAT)
#define GS_TOT (3 * GS_STAGE)

template <int KG, bool GELU_EPI>
__global__ __launch_bounds__(256) void gemm_kernel(
    const __nv_bfloat16* __restrict__ A, const __nv_bfloat16* __restrict__ Bt,
    const float* __restrict__ bias, const float* __restrict__ gamma,
    const float* __restrict__ resid, __nv_bfloat16* __restrict__ outB,
    float* __restrict__ outF, int NG) {
    uint32_t sbase = (uint32_t)__cvta_generic_to_shared(dyn_smem);

    int tid = threadIdx.x;
    int bm = blockIdx.x * GBM, bn = blockIdx.y * GBN;
    int warp = tid >> 5, lane = tid & 31;
    int wm = (warp >> 2) * 64;
    int wn = (warp & 3) * 32;
    int gid = lane >> 2, tq = lane & 3;
    int lrA = ((lane >> 3) & 1) * 8 + (lane & 7);
    int lcA = (lane >> 4) * 8;
    int lrB = lane & 7;
    int lcB = ((lane >> 3) & 1) * 8;

    float acc[4][4][4];
#pragma unroll
    for (int mi = 0; mi < 4; mi++)
#pragma unroll
        for (int ni = 0; ni < 4; ni++)
#pragma unroll
            for (int u = 0; u < 4; u++) acc[mi][ni][u] = 0.f;

    auto load_tile = [&](int kc, int s) {
        unsigned base = sbase + (unsigned)s * GS_STAGE;
#pragma unroll
        for (int it = tid; it < 512; it += 256) {
            int row = it >> 2, q = it & 3;
            unsigned so = (unsigned)((row * GST + q * 8) * 2);
            cpa16(base + so, A + (size_t)(bm + row) * KG + kc + q * 8);
            cpa16(base + GS_MAT + so, Bt + (size_t)(bn + row) * KG + kc + q * 8);
        }
        asm volatile("cp.async.commit_group;\n" ::: "memory");
    };

    constexpr int NIT = KG / GBK;
    load_tile(0, 0);
    load_tile(GBK, 1);
    int sidx = 0;
    for (int i = 0; i < NIT; i++) {
        cp_wait<1>();
        __syncthreads();
        if (i + 2 < NIT) load_tile((i + 2) * GBK, (i + 2) % 3);
        unsigned abase = sbase + (unsigned)sidx * GS_STAGE;
        unsigned bbase = abase + GS_MAT;
#pragma unroll
        for (int ks = 0; ks < 2; ks++) {
            int k0 = ks * 16;
            unsigned av[4][4], bv[4][2];
#pragma unroll
            for (int mi = 0; mi < 4; mi++)
                ldsm4(av[mi][0], av[mi][1], av[mi][2], av[mi][3],
                      abase + (unsigned)(((wm + mi * 16 + lrA) * GST + k0 + lcA) * 2));
#pragma unroll
            for (int ni = 0; ni < 4; ni++)
                ldsm2(bv[ni][0], bv[ni][1],
                      bbase + (unsigned)(((wn + ni * 8 + lrB) * GST + k0 + lcB) * 2));
#pragma unroll
            for (int mi = 0; mi < 4; mi++)
#pragma unroll
                for (int ni = 0; ni < 4; ni++) mma16816(acc[mi][ni], av[mi], bv[ni]);
        }
        sidx = (sidx + 1) % 3;
    }

#pragma unroll
    for (int mi = 0; mi < 4; mi++) {
        int r0 = bm + wm + mi * 16 + gid;
#pragma unroll
        for (int ni = 0; ni < 4; ni++) {
            int c0 = bn + wn + ni * 8 + tq * 2;
            float* a4 = acc[mi][ni];
            if (GELU_EPI) {
                float b0 = bias[c0], b1 = bias[c0 + 1];
                __nv_bfloat162 v0, v1;
                v0.x = __float2bfloat16(gelu_exact(a4[0] + b0));
                v0.y = __float2bfloat16(gelu_exact(a4[1] + b1));
                v1.x = __float2bfloat16(gelu_exact(a4[2] + b0));
                v1.y = __float2bfloat16(gelu_exact(a4[3] + b1));
                *(__nv_bfloat162*)(outB + (size_t)r0 * NG + c0) = v0;
                *(__nv_bfloat162*)(outB + (size_t)(r0 + 8) * NG + c0) = v1;
            } else {
                float b0 = bias[c0], b1 = bias[c0 + 1];
                float g0 = gamma[c0], g1 = gamma[c0 + 1];
                size_t o0 = (size_t)r0 * NG + c0;
                size_t o1 = (size_t)(r0 + 8) * NG + c0;
                float2 r0v = *(const float2*)(resid + o0);
                float2 r1v = *(const float2*)(resid + o1);
                float2 ov0 = {r0v.x + g0 * (a4[0] + b0), r0v.y + g1 * (a4[1] + b1)};
                float2 ov1 = {r1v.x + g0 * (a4[2] + b0), r1v.y + g1 * (a4[3] + b1)};
                *(float2*)(outF + o0) = ov0;
                *(float2*)(outF + o1) = ov1;
            }
        }
    }
}

// ---------------------------------------------------------------------------
extern "C" void kernel_launch(void* const* d_in, const int* in_sizes, int n_in,
                              void* d_out, int out_size) {
    (void)in_sizes; (void)n_in; (void)out_size;
    const float* x     = (const float*)d_in[0];
    const float* n1g   = (const float*)d_in[1];
    const float* n1b   = (const float*)d_in[2];
    const float* wq    = (const float*)d_in[3];
    const float* lnqg  = (const float*)d_in[4];
    const float* lnqb  = (const float*)d_in[5];
    const float* wk    = (const float*)d_in[6];
    const float* lnkg  = (const float*)d_in[7];
    const float* lnkb  = (const float*)d_in[8];
    const float* wv    = (const float*)d_in[9];
    const float* lnvg  = (const float*)d_in[10];
    const float* lnvb  = (const float*)d_in[11];
    const float* wproj = (const float*)d_in[12];
    const float* dw_w  = (const float*)d_in[13];
    const float* dw_b  = (const float*)d_in[14];
    const float* mng   = (const float*)d_in[15];
    const float* mnb   = (const float*)d_in[16];
    const float* pw1   = (const float*)d_in[17];
    const float* pw1b  = (const float*)d_in[18];
    const float* pw2   = (const float*)d_in[19];
    const float* pw2b  = (const float*)d_in[20];
    const float* gam   = (const float*)d_in[21];
    float* out = (float*)d_out;

    float *x1;
    __nv_bfloat16 *m0b, *m1, *hbuf, *w1t, *w2t;
    cudaGetSymbolAddress((void**)&m0b, g_m0b);
    cudaGetSymbolAddress((void**)&x1, g_x1);
    cudaGetSymbolAddress((void**)&m1, g_m1);
    cudaGetSymbolAddress((void**)&hbuf, g_h);
    cudaGetSymbolAddress((void**)&w1t, g_w1t);
    cudaGetSymbolAddress((void**)&w2t, g_w2t);

    cudaFuncSetAttribute(qkv_kernel, cudaFuncAttributeMaxDynamicSharedMemorySize, 62976);
    cudaFuncSetAttribute(gemm_kernel<384, true>,
                         cudaFuncAttributeMaxDynamicSharedMemorySize, GS_TOT);
    cudaFuncSetAttribute(gemm_kernel<1536, false>,
                         cudaFuncAttributeMaxDynamicSharedMemorySize, GS_TOT);

    // 1. QKV (LN1 fused in regs, bf16 window, pairwise conv)
    qkv_kernel<<<NWIN, 256, 62976>>>(x, n1g, n1b, wq, lnqg, lnqb,
                                     wk, lnkg, lnkb, wv, lnvg, lnvb);
    // 2. attention (mma.sync bf16, bf16 out)
    attn_kernel<<<dim3(12, NWIN), 128>>>();
    // 3. proj + residual (bf16 in, fp32 out)
    proj_kernel<<<NWIN, 256>>>(wproj, x);
    // 4. 7x7 depthwise (fp32 in, bf16 out, 8 w-outputs/thread)
    dwconv7_kernel<<<3072, 256>>>(dw_w, dw_b);
    // 5. LN bf16 -> bf16
    ln_bf_kernel<<<8192, 256>>>(m0b, m1, mng, mnb, 1e-6f);
    // 6. weight prep
    prep_kernel<<<2304, 256>>>(pw1, pw2);
    // 7. GEMM1 + GELU
    gemm_kernel<384, true><<<dim3(512, 12), 256, GS_TOT>>>(m1, w1t, pw1b, nullptr,
                                                           nullptr, hbuf, nullptr, 1536);
    // 8. GEMM2 + gamma + residual
    gemm_kernel<1536, false><<<dim3(512, 3), 256, GS_TOT>>>(hbuf, w2t, pw2b, gam, x1,
                                                            nullptr, out, 384);
}

// round 15
// speedup vs baseline: 1.0462x; 1.0183x over previous
#include <cuda_runtime.h>
#include <cuda_bf16.h>
#include <cstdint>

// ---------------------------------------------------------------------------
// ConvSwinTransformerBlock  (B=4, H=W=128, C=384, WS=8, SHIFT=4, HEADS=12)
// R15: R14 + qkv conv weights read via __ldg/L1 (no smem staging, no
//      per-projection barriers, 49KB smem -> 4 blocks/SM).
// ---------------------------------------------------------------------------

#define CC 384
#define NWIN 1024             // 4 * 256

extern __shared__ char dyn_smem[];

// ---------------- scratch (device globals: allocation-guard safe) ----------
__device__ __nv_bfloat16 g_qb [25165824];       // [win*12+hd][64][32]
__device__ __nv_bfloat16 g_kb [25165824];
__device__ __nv_bfloat16 g_vb [25165824];
__device__ __nv_bfloat16 g_aob[25165824];       // attn out, bf16
__device__ float g_x1 [25165824];               // fp32 (residual + dwconv7 in)
__device__ __nv_bfloat16 g_m0b[25165824];       // dwconv7 out, bf16
__device__ __nv_bfloat16 g_m1 [25165824];
__device__ __nv_bfloat16 g_h  [100663296];      // 65536 x 1536
__device__ __nv_bfloat16 g_w1t[589824];         // [1536][384]
__device__ __nv_bfloat16 g_w2t[589824];         // [384][1536]

__device__ __forceinline__ float gelu_exact(float x) {
    return 0.5f * x * (1.0f + erff(x * 0.7071067811865476f));
}
__device__ __forceinline__ unsigned packbf(float a, float b) {
    __nv_bfloat162 v = __floats2bfloat162_rn(a, b);
    return *(unsigned*)&v;
}

// ---------------- LayerNorm bf16->bf16 over C=384 (warp per token) ---------
__global__ void ln_bf_kernel(const __nv_bfloat16* __restrict__ in,
                             __nv_bfloat16* __restrict__ out,
                             const float* __restrict__ g,
                             const float* __restrict__ bta, float eps) {
    int token = blockIdx.x * 8 + (threadIdx.x >> 5);
    int lane = threadIdx.x & 31;
    const __nv_bfloat162* p = (const __nv_bfloat162*)(in + (size_t)token * CC);
    float2 v[6];
    float s = 0.f, s2 = 0.f;
#pragma unroll
    for (int i = 0; i < 6; i++) {
        v[i] = __bfloat1622float2(p[lane + 32 * i]);
        s += v[i].x + v[i].y;
        s2 += v[i].x * v[i].x + v[i].y * v[i].y;
    }
#pragma unroll
    for (int o = 16; o; o >>= 1) {
        s += __shfl_xor_sync(0xffffffffu, s, o);
        s2 += __shfl_xor_sync(0xffffffffu, s2, o);
    }
    float mu = s * (1.f / 384.f);
    float var = s2 * (1.f / 384.f) - mu * mu;
    float rstd = rsqrtf(var + eps);
    __nv_bfloat162* q = (__nv_bfloat162*)(out + (size_t)token * CC);
    const float2* g2 = (const float2*)g;
    const float2* b2 = (const float2*)bta;
#pragma unroll
    for (int i = 0; i < 6; i++) {
        int j = lane + 32 * i;
        float2 gg = g2[j], bb = b2[j];
        q[j] = __floats2bfloat162_rn((v[i].x - mu) * rstd * gg.x + bb.x,
                                     (v[i].y - mu) * rstd * gg.y + bb.y);
    }
}

// ---------------- QKV: LN1(reg) -> bf16 window -> dwconv3x3 -> LN ----------
// smem: xs (64*384 bf16 = 49152 B). Weights come from L1 via __ldg.
__global__ __launch_bounds__(256) void qkv_kernel(
    const float* __restrict__ x, const float* __restrict__ n1g,
    const float* __restrict__ n1b,
    const float* __restrict__ wq, const float* __restrict__ lnqg,
    const float* __restrict__ lnqb,
    const float* __restrict__ wk, const float* __restrict__ lnkg,
    const float* __restrict__ lnkb,
    const float* __restrict__ wv, const float* __restrict__ lnvg,
    const float* __restrict__ lnvb) {
    uint2* xs_u2 = (uint2*)dyn_smem;                       // 96 uint2 per token
    int tid = threadIdx.x;
    int win = blockIdx.x;
    int b = win >> 8, widx = win & 255, wh = widx >> 4, ww = widx & 15;
    int warp = tid >> 5, lane = tid & 31;

    // ---- phase 1: load + LN1 in registers, write bf16 window ----
    for (int t = warp; t < 64; t += 8) {
        int r = t >> 3, cc0 = t & 7;
        int h = (wh * 8 + r + 4) & 127;
        int w = (ww * 8 + cc0 + 4) & 127;
        const float4* src = (const float4*)x + (size_t)(b * 16384 + h * 128 + w) * 96;
        float4 xv[3];
        float s = 0.f, s2 = 0.f;
#pragma unroll
        for (int g = 0; g < 3; g++) {
            xv[g] = __ldg(src + g * 32 + lane);
            s += xv[g].x + xv[g].y + xv[g].z + xv[g].w;
            s2 += xv[g].x * xv[g].x + xv[g].y * xv[g].y +
                  xv[g].z * xv[g].z + xv[g].w * xv[g].w;
        }
#pragma unroll
        for (int o = 16; o; o >>= 1) {
            s += __shfl_xor_sync(0xffffffffu, s, o);
            s2 += __shfl_xor_sync(0xffffffffu, s2, o);
        }
        float mu = s * (1.f / 384.f);
        float var = s2 * (1.f / 384.f) - mu * mu;
        float rstd = rsqrtf(var + 1e-5f);
#pragma unroll
        for (int g = 0; g < 3; g++) {
            int c4 = g * 32 + lane;
            float4 g4 = ((const float4*)n1g)[c4];
            float4 b4 = ((const float4*)n1b)[c4];
            float ox = (xv[g].x - mu) * rstd * g4.x + b4.x;
            float oy = (xv[g].y - mu) * rstd * g4.y + b4.y;
            float oz = (xv[g].z - mu) * rstd * g4.z + b4.z;
            float ow = (xv[g].w - mu) * rstd * g4.w + b4.w;
            uint2 pk;
            pk.x = packbf(ox, oy);
            pk.y = packbf(oz, ow);
            xs_u2[t * 96 + c4] = pk;
        }
    }
    __syncthreads();
    // xs is read-only from here; no more barriers needed.

    const float* Wp[3] = {wq, wk, wv};
    const float* Gg[3] = {lnqg, lnkg, lnvg};
    const float* Bb[3] = {lnqb, lnkb, lnvb};
    __nv_bfloat16* Out[3] = {g_qb, g_kb, g_vb};
    int cc = warp;   // column this warp owns

    for (int p = 0; p < 3; p++) {
        const float4* wsrc = (const float4*)Wp[p];
        float scale = (p == 0) ? 0.17677669529663687f : 1.0f;  // 1/sqrt(32)

        for (int m = 0; m < 4; m++) {
            int rA = 2 * m;                    // token rows rA, rA+1
            float4 a0[3], a1[3];
#pragma unroll
            for (int g = 0; g < 3; g++) {
                a0[g] = make_float4(0.f, 0.f, 0.f, 0.f);
                a1[g] = make_float4(0.f, 0.f, 0.f, 0.f);
            }
            {
                float4 wcur[9], wprev[9];      // scoped: freed before LN
#pragma unroll
                for (int dr2 = 0; dr2 < 4; dr2++) {
                    if (dr2 > 0) {
#pragma unroll
                        for (int i = 0; i < 9; i++) wprev[i] = wcur[i];
                    }
                    if (dr2 <= 2) {
#pragma unroll
                        for (int dc = 0; dc < 3; dc++)
#pragma unroll
                            for (int g = 0; g < 3; g++)
                                wcur[dc * 3 + g] =
                                    __ldg(wsrc + (dr2 * 3 + dc) * 96 + g * 32 + lane);
                    }
                    int rr = rA - 1 + dr2;
                    if (rr < 0 || rr > 7) continue;
                    bool u0 = (dr2 <= 2);      // token row rA uses tap row dr2
                    bool u1 = (dr2 >= 1);      // token row rA+1 uses tap row dr2-1
#pragma unroll
                    for (int dc = 0; dc < 3; dc++) {
                        int c2 = cc + dc - 1;
                        if (c2 < 0 || c2 > 7) continue;
#pragma unroll
                        for (int g = 0; g < 3; g++) {
                            uint2 xv2 = xs_u2[(rr * 8 + c2) * 96 + g * 32 + lane];
                            float2 f01 = __bfloat1622float2(*(__nv_bfloat162*)&xv2.x);
                            float2 f23 = __bfloat1622float2(*(__nv_bfloat162*)&xv2.y);
                            if (u0) {
                                float4 w = wcur[dc * 3 + g];
                                a0[g].x += f01.x * w.x; a0[g].y += f01.y * w.y;
                                a0[g].z += f23.x * w.z; a0[g].w += f23.y * w.w;
                            }
                            if (u1) {
                                float4 w = wprev[dc * 3 + g];
                                a1[g].x += f01.x * w.x; a1[g].y += f01.y * w.y;
                                a1[g].z += f23.x * w.z; a1[g].w += f23.y * w.w;
                            }
                        }
                    }
                }
            }
            // ---- LN + store for the two tokens (fused sum/sumsq) ----
#pragma unroll
            for (int half = 0; half < 2; half++) {
                float4* vv = half ? a1 : a0;
                int t = (rA + half) * 8 + cc;
                float s = 0.f, s2 = 0.f;
#pragma unroll
                for (int g = 0; g < 3; g++) {
                    s += vv[g].x + vv[g].y + vv[g].z + vv[g].w;
                    s2 += vv[g].x * vv[g].x + vv[g].y * vv[g].y +
                          vv[g].z * vv[g].z + vv[g].w * vv[g].w;
                }
#pragma unroll
                for (int o = 16; o; o >>= 1) {
                    s += __shfl_xor_sync(0xffffffffu, s, o);
                    s2 += __shfl_xor_sync(0xffffffffu, s2, o);
                }
                float mu = s * (1.f / 384.f);
                float var = s2 * (1.f / 384.f) - mu * mu;
                float rstd = rsqrtf(var + 1e-5f);
#pragma unroll
                for (int g = 0; g < 3; g++) {
                    int c4 = g * 32 + lane;
                    float4 g4 = ((const float4*)Gg[p])[c4];
                    float4 b4 = ((const float4*)Bb[p])[c4];
                    float ox = ((vv[g].x - mu) * rstd * g4.x + b4.x) * scale;
                    float oy = ((vv[g].y - mu) * rstd * g4.y + b4.y) * scale;
                    float oz = ((vv[g].z - mu) * rstd * g4.z + b4.z) * scale;
                    float ow = ((vv[g].w - mu) * rstd * g4.w + b4.w) * scale;
                    int head = c4 >> 3, d0 = (c4 & 7) * 4;
                    __nv_bfloat16* dst = Out[p] +
                        ((size_t)(win * 12 + head) * 64 + t) * 32 + d0;
                    uint2 pk;
                    pk.x = packbf(ox, oy);
                    pk.y = packbf(oz, ow);
                    *(uint2*)dst = pk;
                }
            }
        }
    }
}

// ---------------- mma helpers ----------------------------------------------
__device__ __forceinline__ void mma16816(float* c, const unsigned* a, const unsigned* b) {
    asm volatile(
        "mma.sync.aligned.m16n8k16.row.col.f32.bf16.bf16.f32 "
        "{%0,%1,%2,%3}, {%4,%5,%6,%7}, {%8,%9}, {%0,%1,%2,%3};\n"
        : "+f"(c[0]), "+f"(c[1]), "+f"(c[2]), "+f"(c[3])
        : "r"(a[0]), "r"(a[1]), "r"(a[2]), "r"(a[3]), "r"(b[0]), "r"(b[1]));
}
__device__ __forceinline__ void ldsm4(unsigned& r0, unsigned& r1, unsigned& r2,
                                      unsigned& r3, uint32_t a) {
    asm volatile("ldmatrix.sync.aligned.m8n8.x4.shared.b16 {%0,%1,%2,%3}, [%4];\n"
                 : "=r"(r0), "=r"(r1), "=r"(r2), "=r"(r3) : "r"(a));
}
__device__ __forceinline__ void ldsm2(unsigned& r0, unsigned& r1, uint32_t a) {
    asm volatile("ldmatrix.sync.aligned.m8n8.x2.shared.b16 {%0,%1}, [%2];\n"
                 : "=r"(r0), "=r"(r1) : "r"(a));
}
__device__ __forceinline__ void cpa16(uint32_t s, const void* g) {
    asm volatile("cp.async.cg.shared.global [%0], [%1], 16;\n" :: "r"(s), "l"(g) : "memory");
}
template <int N>
__device__ __forceinline__ void cp_wait() {
    asm volatile("cp.async.wait_group %0;\n" :: "n"(N) : "memory");
}

// ---------------- attention: mma.sync bf16, block per (win, head) ----------
__device__ __forceinline__ int swin_reg(int x) { return (x < 120) ? 0 : ((x < 124) ? 1 : 2); }

__global__ __launch_bounds__(128) void attn_kernel() {
    __shared__ __align__(16) __nv_bfloat16 Qs[64 * 40];
    __shared__ __align__(16) __nv_bfloat16 Ks[64 * 40];
    __shared__ __align__(16) __nv_bfloat16 VT[32 * 72];
    int tid = threadIdx.x;
    int hd = blockIdx.x, win = blockIdx.y;
    int widx = win & 255, wh = widx >> 4, ww = widx & 15;
    int warp = tid >> 5, lane = tid & 31;

    const uint4* qg = (const uint4*)(g_qb + (size_t)(win * 12 + hd) * 2048);
    const uint4* kg = (const uint4*)(g_kb + (size_t)(win * 12 + hd) * 2048);
    const uint4* vg = (const uint4*)(g_vb + (size_t)(win * 12 + hd) * 2048);
    for (int i = tid; i < 256; i += 128) {
        int row = i >> 2, q = i & 3;
        *(uint4*)(Qs + row * 40 + q * 8) = qg[i];
        *(uint4*)(Ks + row * 40 + q * 8) = kg[i];
        uint4 v = vg[i];
        const __nv_bfloat16* vb = (const __nv_bfloat16*)&v;
        int d0 = q * 8;
#pragma unroll
        for (int j = 0; j < 8; j++) VT[(d0 + j) * 72 + row] = vb[j];
    }
    __syncthreads();

    uint32_t qb = (uint32_t)__cvta_generic_to_shared(Qs);
    uint32_t kb = (uint32_t)__cvta_generic_to_shared(Ks);
    uint32_t vtb = (uint32_t)__cvta_generic_to_shared(VT);
    int gid = lane >> 2, tq = lane & 3;
    int lrA = ((lane >> 3) & 1) * 8 + (lane & 7);
    int lcA = (lane >> 4) * 8;
    int lrB = lane & 7;
    int lcB = ((lane >> 3) & 1) * 8;
    int m0 = warp * 16;

    // ---- S = Q @ K^T  (16 rows per warp) ----
    unsigned aQ[2][4];
#pragma unroll
    for (int ks = 0; ks < 2; ks++)
        ldsm4(aQ[ks][0], aQ[ks][1], aQ[ks][2], aQ[ks][3],
              qb + (unsigned)(((m0 + lrA) * 40 + ks * 16 + lcA) * 2));
    float sc[8][4];
#pragma unroll
    for (int nt = 0; nt < 8; nt++)
#pragma unroll
        for (int u = 0; u < 4; u++) sc[nt][u] = 0.f;
#pragma unroll
    for (int nt = 0; nt < 8; nt++) {
#pragma unroll
        for (int ks = 0; ks < 2; ks++) {
            unsigned b[2];
            ldsm2(b[0], b[1], kb + (unsigned)(((nt * 8 + lrB) * 40 + ks * 16 + lcB) * 2));
            mma16816(sc[nt], aQ[ks], b);
        }
    }

    // ---- mask + softmax (rows r0=m0+gid, r1=r0+8) ----
    int r0 = m0 + gid, r1 = r0 + 8;
    bool boundary = (wh == 15) || (ww == 15);
    if (boundary) {
        int l0 = swin_reg(wh * 8 + (r0 >> 3)) * 3 + swin_reg(ww * 8 + (r0 & 7));
        int l1 = swin_reg(wh * 8 + (r1 >> 3)) * 3 + swin_reg(ww * 8 + (r1 & 7));
#pragma unroll
        for (int nt = 0; nt < 8; nt++) {
#pragma unroll
            for (int j = 0; j < 2; j++) {
                int col = nt * 8 + tq * 2 + j;
                int lc = swin_reg(wh * 8 + (col >> 3)) * 3 + swin_reg(ww * 8 + (col & 7));
                if (lc != l0) sc[nt][j] -= 100.f;
                if (lc != l1) sc[nt][2 + j] -= 100.f;
            }
        }
    }
    float mx0 = -1e30f, mx1 = -1e30f;
#pragma unroll
    for (int nt = 0; nt < 8; nt++) {
        mx0 = fmaxf(mx0, fmaxf(sc[nt][0], sc[nt][1]));
        mx1 = fmaxf(mx1, fmaxf(sc[nt][2], sc[nt][3]));
    }
#pragma unroll
    for (int o = 1; o <= 2; o <<= 1) {
        mx0 = fmaxf(mx0, __shfl_xor_sync(0xffffffffu, mx0, o));
        mx1 = fmaxf(mx1, __shfl_xor_sync(0xffffffffu, mx1, o));
    }
    float s0 = 0.f, s1 = 0.f;
#pragma unroll
    for (int nt = 0; nt < 8; nt++) {
        sc[nt][0] = __expf(sc[nt][0] - mx0); s0 += sc[nt][0];
        sc[nt][1] = __expf(sc[nt][1] - mx0); s0 += sc[nt][1];
        sc[nt][2] = __expf(sc[nt][2] - mx1); s1 += sc[nt][2];
        sc[nt][3] = __expf(sc[nt][3] - mx1); s1 += sc[nt][3];
    }
#pragma unroll
    for (int o = 1; o <= 2; o <<= 1) {
        s0 += __shfl_xor_sync(0xffffffffu, s0, o);
        s1 += __shfl_xor_sync(0xffffffffu, s1, o);
    }
    float inv0 = 1.f / s0, inv1 = 1.f / s1;

    // ---- P (A-fragments) ----
    unsigned aP[4][4];
#pragma unroll
    for (int kc = 0; kc < 4; kc++) {
        aP[kc][0] = packbf(sc[2 * kc][0] * inv0, sc[2 * kc][1] * inv0);
        aP[kc][1] = packbf(sc[2 * kc][2] * inv1, sc[2 * kc][3] * inv1);
        aP[kc][2] = packbf(sc[2 * kc + 1][0] * inv0, sc[2 * kc + 1][1] * inv0);
        aP[kc][3] = packbf(sc[2 * kc + 1][2] * inv1, sc[2 * kc + 1][3] * inv1);
    }

    // ---- O = P @ V ----
    float av[4][4];
#pragma unroll
    for (int nj = 0; nj < 4; nj++)
#pragma unroll
        for (int u = 0; u < 4; u++) av[nj][u] = 0.f;
#pragma unroll
    for (int nj = 0; nj < 4; nj++) {
#pragma unroll
        for (int kc = 0; kc < 4; kc++) {
            unsigned b[2];
            ldsm2(b[0], b[1], vtb + (unsigned)(((nj * 8 + lrB) * 72 + kc * 16 + lcB) * 2));
            mma16816(av[nj], aP[kc], b);
        }
    }

    // ---- write O (bf16, token-major for proj) ----
    __nv_bfloat16* dst0 = g_aob + ((size_t)(win * 64 + r0)) * 384 + hd * 32;
    __nv_bfloat16* dst1 = g_aob + ((size_t)(win * 64 + r1)) * 384 + hd * 32;
#pragma unroll
    for (int nj = 0; nj < 4; nj++) {
        *(unsigned*)(dst0 + nj * 8 + tq * 2) = packbf(av[nj][0], av[nj][1]);
        *(unsigned*)(dst1 + nj * 8 + tq * 2) = packbf(av[nj][2], av[nj][3]);
    }
}

// ---------------- proj: dwconv3x3 + GELU + unshift + residual (bf16 in) ----
__global__ __launch_bounds__(256) void proj_kernel(const float* __restrict__ wproj,
                                                   const float* __restrict__ x_in) {
    __shared__ float ws[3456];
    int tid = threadIdx.x;
    int win = blockIdx.x;
    int b = win >> 8, widx = win & 255, wh = widx >> 4, ww = widx & 15;

    for (int i = tid; i < 3456; i += 256) ws[i] = wproj[i];
    __syncthreads();

    const uint2* src = (const uint2*)g_aob + (size_t)(win * 64) * 96;
    const float4* ws4 = (const float4*)ws;
    for (int it = tid; it < 6144; it += 256) {
        int t = it / 96, c4 = it - t * 96;
        int r = t >> 3, cc = t & 7;
        float4 acc = {0.f, 0.f, 0.f, 0.f};
#pragma unroll
        for (int dr = 0; dr < 3; dr++) {
            int rr = r + dr - 1;
            if (rr < 0 || rr > 7) continue;
#pragma unroll
            for (int dc = 0; dc < 3; dc++) {
                int c2 = cc + dc - 1;
                if (c2 < 0 || c2 > 7) continue;
                uint2 xv2 = __ldg(src + (rr * 8 + c2) * 96 + c4);
                float2 f01 = __bfloat1622float2(*(__nv_bfloat162*)&xv2.x);
                float2 f23 = __bfloat1622float2(*(__nv_bfloat162*)&xv2.y);
                float4 wv4 = ws4[(dr * 3 + dc) * 96 + c4];
                acc.x += f01.x * wv4.x; acc.y += f01.y * wv4.y;
                acc.z += f23.x * wv4.z; acc.w += f23.y * wv4.w;
            }
        }
        int h = (wh * 8 + r + 4) & 127;
        int w = (ww * 8 + cc + 4) & 127;
        size_t gi = (size_t)(b * 16384 + h * 128 + w) * 96 + c4;
        float4 xv = ((const float4*)x_in)[gi];
        float4 o;
        o.x = xv.x + gelu_exact(acc.x);
        o.y = xv.y + gelu_exact(acc.y);
        o.z = xv.z + gelu_exact(acc.z);
        o.w = xv.w + gelu_exact(acc.w);
        ((float4*)g_x1)[gi] = o;
    }
}

// ---------------- 7x7 depthwise conv + bias (1h x 8w per thread) -----------
__global__ __launch_bounds__(256) void dwconv7_kernel(const float* __restrict__ w7,
                                                      const float* __restrict__ bias) {
    int idx = blockIdx.x * 256 + threadIdx.x;    // 786,432 threads
    int c4 = idx % 96;
    int t8 = idx / 96;                           // 0..8191
    int b = t8 >> 11, rem = t8 & 2047;
    int h = rem >> 4, w0 = (rem & 15) * 8;
    const float4* x4 = (const float4*)g_x1;
    const float4* wp4 = (const float4*)w7;
    float4 bz = ((const float4*)bias)[c4];
    float4 acc[8] = {bz, bz, bz, bz, bz, bz, bz, bz};
#pragma unroll
    for (int dr = 0; dr < 7; dr++) {
        int hh = h + dr - 3;
        if ((unsigned)hh >= 128u) continue;
        float4 wt[7];
#pragma unroll
        for (int dc = 0; dc < 7; dc++) wt[dc] = wp4[(dr * 7 + dc) * 96 + c4];
        const float4* rowp = x4 + (size_t)((b << 14) + (hh << 7)) * 96 + c4;
#pragma unroll
        for (int j = 0; j < 14; j++) {
            int c = w0 + j - 3;
            if ((unsigned)c >= 128u) continue;
            float4 xv = __ldg(rowp + (size_t)c * 96);
#pragma unroll
            for (int o = 0; o < 8; o++) {
                int tap = j - o;
                if (tap >= 0 && tap < 7) {
                    acc[o].x += xv.x * wt[tap].x; acc[o].y += xv.y * wt[tap].y;
                    acc[o].z += xv.z * wt[tap].z; acc[o].w += xv.w * wt[tap].w;
                }
            }
        }
    }
#pragma unroll
    for (int o = 0; o < 8; o++) {
        int token = (b << 14) + (h << 7) + w0 + o;
        uint2 pk;
        pk.x = packbf(acc[o].x, acc[o].y);
        pk.y = packbf(acc[o].z, acc[o].w);
        ((uint2*)g_m0b)[(size_t)token * 96 + c4] = pk;
    }
}

// ---------------- weight prep: transpose + bf16 ----------------------------
__global__ void prep_kernel(const float* __restrict__ pw1, const float* __restrict__ pw2) {
    int i = blockIdx.x * 256 + threadIdx.x;
    if (i < 589824) {
        int n = i / 384, k = i - n * 384;
        g_w1t[i] = __float2bfloat16(pw1[k * 1536 + n]);
        int n2 = i / 1536, k2 = i - n2 * 1536;
        g_w2t[i] = __float2bfloat16(pw2[k2 * 384 + n2]);
    }
}

// ---------------- bf16 GEMM: 3-stage cp.async + ldmatrix + mma.sync --------
#define GBM 128
#define GBN 128
#define GBK 32
#define GST 40
#define GS_MAT (GBM * GST * 2)
#define GS_STAGE (2 * GS_MAT)
#define GS_TOT (3 * GS_STAGE)

template <int KG, bool GELU_EPI>
__global__ __launch_bounds__(256) void gemm_kernel(
    const __nv_bfloat16* __restrict__ A, const __nv_bfloat16* __restrict__ Bt,
    const float* __restrict__ bias, const float* __restrict__ gamma,
    const float* __restrict__ resid, __nv_bfloat16* __restrict__ outB,
    float* __restrict__ outF, int NG) {
    uint32_t sbase = (uint32_t)__cvta_generic_to_shared(dyn_smem);

    int tid = threadIdx.x;
    int bm = blockIdx.x * GBM, bn = blockIdx.y * GBN;
    int warp = tid >> 5, lane = tid & 31;
    int wm = (warp >> 2) * 64;
    int wn = (warp & 3) * 32;
    int gid = lane >> 2, tq = lane & 3;
    int lrA = ((lane >> 3) & 1) * 8 + (lane & 7);
    int lcA = (lane >> 4) * 8;
    int lrB = lane & 7;
    int lcB = ((lane >> 3) & 1) * 8;

    float acc[4][4][4];
#pragma unroll
    for (int mi = 0; mi < 4; mi++)
#pragma unroll
        for (int ni = 0; ni < 4; ni++)
#pragma unroll
            for (int u = 0; u < 4; u++) acc[mi][ni][u] = 0.f;

    auto load_tile = [&](int kc, int s) {
        unsigned base = sbase + (unsigned)s * GS_STAGE;
#pragma unroll
        for (int it = tid; it < 512; it += 256) {
            int row = it >> 2, q = it & 3;
            unsigned so = (unsigned)((row * GST + q * 8) * 2);
            cpa16(base + so, A + (size_t)(bm + row) * KG + kc + q * 8);
            cpa16(base + GS_MAT + so, Bt + (size_t)(bn + row) * KG + kc + q * 8);
        }
        asm volatile("cp.async.commit_group;\n" ::: "memory");
    };

    constexpr int NIT = KG / GBK;
    load_tile(0, 0);
    load_tile(GBK, 1);
    int sidx = 0;
    for (int i = 0; i < NIT; i++) {
        cp_wait<1>();
        __syncthreads();
        if (i + 2 < NIT) load_tile((i + 2) * GBK, (i + 2) % 3);
        unsigned abase = sbase + (unsigned)sidx * GS_STAGE;
        unsigned bbase = abase + GS_MAT;
#pragma unroll
        for (int ks = 0; ks < 2; ks++) {
            int k0 = ks * 16;
            unsigned av[4][4], bv[4][2];
#pragma unroll
            for (int mi = 0; mi < 4; mi++)
                ldsm4(av[mi][0], av[mi][1], av[mi][2], av[mi][3],
                      abase + (unsigned)(((wm + mi * 16 + lrA) * GST + k0 + lcA) * 2));
#pragma unroll
            for (int ni = 0; ni < 4; ni++)
                ldsm2(bv[ni][0], bv[ni][1],
                      bbase + (unsigned)(((wn + ni * 8 + lrB) * GST + k0 + lcB) * 2));
#pragma unroll
            for (int mi = 0; mi < 4; mi++)
#pragma unroll
                for (int ni = 0; ni < 4; ni++) mma16816(acc[mi][ni], av[mi], bv[ni]);
        }
        sidx = (sidx + 1) % 3;
    }

#pragma unroll
    for (int mi = 0; mi < 4; mi++) {
        int r0 = bm + wm + mi * 16 + gid;
#pragma unroll
        for (int ni = 0; ni < 4; ni++) {
            int c0 = bn + wn + ni * 8 + tq * 2;
            float* a4 = acc[mi][ni];
            if (GELU_EPI) {
                float b0 = bias[c0], b1 = bias[c0 + 1];
                __nv_bfloat162 v0, v1;
                v0.x = __float2bfloat16(gelu_exact(a4[0] + b0));
                v0.y = __float2bfloat16(gelu_exact(a4[1] + b1));
                v1.x = __float2bfloat16(gelu_exact(a4[2] + b0));
                v1.y = __float2bfloat16(gelu_exact(a4[3] + b1));
                *(__nv_bfloat162*)(outB + (size_t)r0 * NG + c0) = v0;
                *(__nv_bfloat162*)(outB + (size_t)(r0 + 8) * NG + c0) = v1;
            } else {
                float b0 = bias[c0], b1 = bias[c0 + 1];
                float g0 = gamma[c0], g1 = gamma[c0 + 1];
                size_t o0 = (size_t)r0 * NG + c0;
                size_t o1 = (size_t)(r0 + 8) * NG + c0;
                float2 r0v = *(const float2*)(resid + o0);
                float2 r1v = *(const float2*)(resid + o1);
                float2 ov0 = {r0v.x + g0 * (a4[0] + b0), r0v.y + g1 * (a4[1] + b1)};
                float2 ov1 = {r1v.x + g0 * (a4[2] + b0), r1v.y + g1 * (a4[3] + b1)};
                *(float2*)(outF + o0) = ov0;
                *(float2*)(outF + o1) = ov1;
            }
        }
    }
}

// ---------------------------------------------------------------------------
extern "C" void kernel_launch(void* const* d_in, const int* in_sizes, int n_in,
                              void* d_out, int out_size) {
    (void)in_sizes; (void)n_in; (void)out_size;
    const float* x     = (const float*)d_in[0];
    const float* n1g   = (const float*)d_in[1];
    const float* n1b   = (const float*)d_in[2];
    const float* wq    = (const float*)d_in[3];
    const float* lnqg  = (const float*)d_in[4];
    const float* lnqb  = (const float*)d_in[5];
    const float* wk    = (const float*)d_in[6];
    const float* lnkg  = (const float*)d_in[7];
    const float* lnkb  = (const float*)d_in[8];
    const float* wv    = (const float*)d_in[9];
    const float* lnvg  = (const float*)d_in[10];
    const float* lnvb  = (const float*)d_in[11];
    const float* wproj = (const float*)d_in[12];
    const float* dw_w  = (const float*)d_in[13];
    const float* dw_b  = (const float*)d_in[14];
    const float* mng   = (const float*)d_in[15];
    const float* mnb   = (const float*)d_in[16];
    const float* pw1   = (const float*)d_in[17];
    const float* pw1b  = (const float*)d_in[18];
    const float* pw2   = (const float*)d_in[19];
    const float* pw2b  = (const float*)d_in[20];
    const float* gam   = (const float*)d_in[21];
    float* out = (float*)d_out;

    float *x1;
    __nv_bfloat16 *m0b, *m1, *hbuf, *w1t, *w2t;
    cudaGetSymbolAddress((void**)&m0b, g_m0b);
    cudaGetSymbolAddress((void**)&x1, g_x1);
    cudaGetSymbolAddress((void**)&m1, g_m1);
    cudaGetSymbolAddress((void**)&hbuf, g_h);
    cudaGetSymbolAddress((void**)&w1t, g_w1t);
    cudaGetSymbolAddress((void**)&w2t, g_w2t);

    cudaFuncSetAttribute(qkv_kernel, cudaFuncAttributeMaxDynamicSharedMemorySize, 49152);
    cudaFuncSetAttribute(gemm_kernel<384, true>,
                         cudaFuncAttributeMaxDynamicSharedMemorySize, GS_TOT);
    cudaFuncSetAttribute(gemm_kernel<1536, false>,
                         cudaFuncAttributeMaxDynamicSharedMemorySize, GS_TOT);

    // 1. QKV (LN1 fused in regs, bf16 window, weights via L1)
    qkv_kernel<<<NWIN, 256, 49152>>>(x, n1g, n1b, wq, lnqg, lnqb,
                                     wk, lnkg, lnkb, wv, lnvg, lnvb);
    // 2. attention (mma.sync bf16, bf16 out)
    attn_kernel<<<dim3(12, NWIN), 128>>>();
    // 3. proj + residual (bf16 in, fp32 out)
    proj_kernel<<<NWIN, 256>>>(wproj, x);
    // 4. 7x7 depthwise (fp32 in, bf16 out, 8 w-outputs/thread)
    dwconv7_kernel<<<3072, 256>>>(dw_w, dw_b);
    // 5. LN bf16 -> bf16
    ln_bf_kernel<<<8192, 256>>>(m0b, m1, mng, mnb, 1e-6f);
    // 6. weight prep
    prep_kernel<<<2304, 256>>>(pw1, pw2);
    // 7. GEMM1 + GELU
    gemm_kernel<384, true><<<dim3(512, 12), 256, GS_TOT>>>(m1, w1t, pw1b, nullptr,
                                                           nullptr, hbuf, nullptr, 1536);
    // 8. GEMM2 + gamma + residual
    gemm_kernel<1536, false><<<dim3(512, 3), 256, GS_TOT>>>(hbuf, w2t, pw2b, gam, x1,
                                                            nullptr, out, 384);
}